// round 13
// baseline (speedup 1.0000x reference)
#include <cuda_runtime.h>
#include <cuda_bf16.h>
#include <cstdint>

#define NWIN  4096
#define CCH   192
#define HDIM  448
#define HWSZ  (448*448)
#define NHEAD 6
#define HD    32
#define NT    49
#define CPAD  196
#define SROW  52
#define SCOFF 2816
#define XST   200      // bf16 row stride (400B rows, conflict-free ldmatrix)

// ---- device scratch ----
__device__ __align__(16) float g_q[(size_t)NWIN * NT * CCH];
__device__ __align__(16) float g_k[(size_t)NWIN * NT * CCH];
__device__ __align__(16) float g_v[(size_t)NWIN * NT * CCH];
__device__ __align__(16) __nv_bfloat16 g_qkvw[2 * 576 * 192];   // [split][oc][c]
__device__ __align__(16) __nv_bfloat16 g_projw[2 * 192 * 192];  // [split][oc][c]
__device__ __align__(16) __nv_bfloat16 g_ao[(size_t)NWIN * 2 * 64 * XST]; // [win][split][row][c]

// ---- helpers ----
__device__ __forceinline__ uint32_t smem_u32(const void* p) {
    uint32_t a;
    asm("{ .reg .u64 t; cvta.to.shared.u64 t, %1; cvt.u32.u64 %0, t; }" : "=r"(a) : "l"(p));
    return a;
}
#define LDSM4(r, a) asm volatile("ldmatrix.sync.aligned.m8n8.x4.shared.b16 {%0,%1,%2,%3}, [%4];" \
    : "=r"((r)[0]), "=r"((r)[1]), "=r"((r)[2]), "=r"((r)[3]) : "r"(a))
#define MMA_BF16_R(d, A, b0, b1) asm volatile( \
    "mma.sync.aligned.m16n8k16.row.col.f32.bf16.bf16.f32 " \
    "{%0,%1,%2,%3}, {%4,%5,%6,%7}, {%8,%9}, {%0,%1,%2,%3};" \
    : "+f"((d)[0]), "+f"((d)[1]), "+f"((d)[2]), "+f"((d)[3]) \
    : "r"((A)[0]), "r"((A)[1]), "r"((A)[2]), "r"((A)[3]), "r"(b0), "r"(b1))

__device__ __forceinline__ void bf16_split(float v, __nv_bfloat16& hi, __nv_bfloat16& lo) {
    hi = __float2bfloat16(v);
    lo = __float2bfloat16(v - __bfloat162float(hi));
}

// ============================================================================
// Kernel 0: weight prep
// ============================================================================
__global__ void prep_kernel(const float* __restrict__ qkvW, const float* __restrict__ projW) {
    int i = blockIdx.x * blockDim.x + threadIdx.x;
    if (i < 576 * 192) {
        __nv_bfloat16 hi, lo; bf16_split(qkvW[i], hi, lo);
        g_qkvw[i] = hi; g_qkvw[576 * 192 + i] = lo;
    } else {
        i -= 576 * 192;
        if (i < 192 * 192) {
            __nv_bfloat16 hi, lo; bf16_split(projW[i], hi, lo);
            g_projw[i] = hi; g_projw[192 * 192 + i] = lo;
        }
    }
}

// ============================================================================
// Kernel 1: QKV GEMM — M=64 (1 window), 512 thr, 2 CTAs/SM, 9 stages of 64 oc
// smem: Xh 25600 | Xl 25600 | Wh 25600 | Wl 25600 = 102400 B
// ============================================================================
#define GEMM_SMEM 102400

__global__ __launch_bounds__(512, 2)
void qkv_kernel(const float* __restrict__ x, const float* __restrict__ qkvB)
{
    extern __shared__ char smem[];
    __nv_bfloat16* Xh = (__nv_bfloat16*)smem;
    __nv_bfloat16* Xl = (__nv_bfloat16*)(smem + 25600);
    const uint32_t sb = smem_u32(smem);
    const int tid = threadIdx.x, lane = tid & 31, warp = tid >> 5;
    const int win = blockIdx.x;
    const int wy = win >> 6, wx = win & 63;
    const int mw = warp & 3, nw = warp >> 2;

    // gather shifted window, bf16-split
    for (int idx = tid; idx < NT * CCH; idx += 512) {
        int c = idx / NT, t = idx - c * NT;
        int r = t / 7, cc = t - r * 7;
        int h = wy * 7 + r + 3; if (h >= HDIM) h -= HDIM;
        int w = wx * 7 + cc + 3; if (w >= HDIM) w -= HDIM;
        __nv_bfloat16 hi, lo; bf16_split(x[c * HWSZ + h * HDIM + w], hi, lo);
        int off = t * XST + c;
        Xh[off] = hi; Xl[off] = lo;
    }
    for (int idx = tid; idx < 15 * CCH; idx += 512) {   // pad rows 49..63
        int pr = idx / CCH, c = idx - pr * CCH;
        int off = (49 + pr) * XST + c;
        Xh[off] = __float2bfloat16(0.f); Xl[off] = __float2bfloat16(0.f);
    }
    __syncthreads();

    // fragment addresses
    const uint32_t aoffh = sb + (uint32_t)(mw * 16 + (lane & 15)) * 400 + (lane >> 4) * 16;
    const uint32_t aoffl = aoffh + 25600;
    const uint32_t boffh = sb + 51200
        + (uint32_t)(nw * 16 + (lane & 7) + ((lane >> 4) << 3)) * 400 + ((lane >> 3) & 1) * 16;
    const uint32_t boffl = boffh + 25600;

    for (int s = 0; s < 9; s++) {
        // stage 64 oc rows (hi+lo): 2 x 1536 uint4
        for (int i = tid; i < 3072; i += 512) {
            int split = i >= 1536, j = i - split * 1536;
            int r = j / 24, p = j - r * 24;
            __nv_bfloat16* dst = (__nv_bfloat16*)(smem + 51200 + split * 25600);
            ((uint4*)(dst + r * XST))[p] =
                ((const uint4*)(g_qkvw + split * (576 * 192) + (s * 64 + r) * 192))[p];
        }
        __syncthreads();

        float acc[2][4];
        #pragma unroll
        for (int b = 0; b < 2; b++)
            #pragma unroll
            for (int e = 0; e < 4; e++) acc[b][e] = 0.f;

        #pragma unroll 2
        for (int k = 0; k < 12; k++) {
            uint32_t ah[4], al[4], b4h[4], b4l[4];
            LDSM4(ah, aoffh + k * 32);
            LDSM4(al, aoffl + k * 32);
            LDSM4(b4h, boffh + k * 32);
            LDSM4(b4l, boffl + k * 32);
            MMA_BF16_R(acc[0], ah, b4h[0], b4h[1]);
            MMA_BF16_R(acc[1], ah, b4h[2], b4h[3]);
            MMA_BF16_R(acc[0], ah, b4l[0], b4l[1]);
            MMA_BF16_R(acc[1], ah, b4l[2], b4l[3]);
            MMA_BF16_R(acc[0], al, b4h[0], b4h[1]);
            MMA_BF16_R(acc[1], al, b4h[2], b4h[3]);
        }

        // epilogue: fp32 scratch with bias (+ q scale)
        const int g = lane >> 2, c2 = (lane & 3) * 2;
        #pragma unroll
        for (int nt = 0; nt < 2; nt++) {
            int col = s * 64 + nw * 16 + nt * 8 + c2;
            int buf = col / 192, ch = col - buf * 192;
            float scl = (buf == 0) ? 0.17677669529663687f : 1.0f;
            float* base = (buf == 0) ? g_q : (buf == 1) ? g_k : g_v;
            float b0 = qkvB[col], b1 = qkvB[col + 1];
            #pragma unroll
            for (int rr = 0; rr < 2; rr++) {
                int row = mw * 16 + g + rr * 8;
                if (row < NT) {
                    float2 o;
                    o.x = (acc[nt][rr * 2 + 0] + b0) * scl;
                    o.y = (acc[nt][rr * 2 + 1] + b1) * scl;
                    *(float2*)(base + ((size_t)win * NT + row) * CCH + ch) = o;
                }
            }
        }
        __syncthreads();
    }
}

// ============================================================================
// Kernel 2: attention (per window), writes ao as bf16 splits (row-major)
// ============================================================================
constexpr int ATTN_FLOATS = 3 * NT * CPAD + 2 * SCOFF + 64;

__global__ __launch_bounds__(512, 1)
void attn_kernel(const float* __restrict__ table)
{
    extern __shared__ float smf[];
    float* qs = smf;
    float* ks = qs + NT * CPAD;
    float* vs = ks + NT * CPAD;
    float* sc = vs + NT * CPAD;
    int*   mreg = (int*)(sc + 2 * SCOFF);

    const int tid  = threadIdx.x;
    const int lane = tid & 31;
    const int warp = tid >> 5;
    const int w8   = warp & 7;
    const int half = warp >> 3;
    const int win = blockIdx.x;
    const int wy = win >> 6, wx = win & 63;

    if (tid < NT) {
        int r = tid / 7, cc = tid - (tid / 7) * 7;
        int hs = wy * 7 + r, ws = wx * 7 + cc;
        int rb = (hs >= 441) + (hs >= 445);
        int cb = (ws >= 441) + (ws >= 445);
        mreg[tid] = rb * 3 + cb;
    }
    {
        const float4* gq = (const float4*)(g_q + (size_t)win * NT * CCH);
        const float4* gk = (const float4*)(g_k + (size_t)win * NT * CCH);
        const float4* gv = (const float4*)(g_v + (size_t)win * NT * CCH);
        for (int i4 = tid; i4 < NT * 48; i4 += 512) {
            int t = i4 / 48, c4 = i4 - t * 48;
            ((float4*)(qs + t * CPAD))[c4] = gq[i4];
            ((float4*)(ks + t * CPAD))[c4] = gk[i4];
            ((float4*)(vs + t * CPAD))[c4] = gv[i4];
        }
    }
    __syncthreads();

    __nv_bfloat16* aoim = g_ao + (size_t)win * 2 * 64 * XST;

    for (int hp = 0; hp < 3; hp++) {
        const int h  = hp * 2 + half;
        const int kb = h * HD;
        float* shc = sc + half * SCOFF;

        for (int ig = w8; ig < 13; ig += 8) {
            int i0 = ig * 4;
            float a2[4][2] = {{0,0},{0,0},{0,0},{0,0}};
            const int j2 = lane + 32;
            const bool j2v = (j2 < NT);
            #pragma unroll
            for (int d = 0; d < HD; d += 4) {
                float4 k0 = *(const float4*)(ks + lane * CPAD + kb + d);
                float4 k1 = make_float4(0.f, 0.f, 0.f, 0.f);
                if (j2v) k1 = *(const float4*)(ks + j2 * CPAD + kb + d);
                #pragma unroll
                for (int ii = 0; ii < 4; ii++) {
                    const float4 q4 = *(const float4*)(qs + (i0 + ii) * CPAD + kb + d);
                    a2[ii][0] += q4.x*k0.x + q4.y*k0.y + q4.z*k0.z + q4.w*k0.w;
                    a2[ii][1] += q4.x*k1.x + q4.y*k1.y + q4.z*k1.z + q4.w*k1.w;
                }
            }
            #pragma unroll
            for (int ii = 0; ii < 4; ii++) {
                int i = i0 + ii;
                if (i >= NT) break;
                int ri = i / 7, ci = i - ri * 7;
                int mi = mreg[i];
                #pragma unroll
                for (int jj = 0; jj < 2; jj++) {
                    int j = lane + jj * 32;
                    if (j >= NT) continue;
                    int rj = j / 7, cj = j - rj * 7;
                    int rel = (ri - rj) + (ci - cj);
                    if (rel < 0) rel += 169;
                    float bi = table[rel * NHEAD + h];
                    float msk = (mi == mreg[j]) ? 0.0f : -100.0f;
                    shc[i * SROW + j] = a2[ii][jj] + bi + msk;
                }
            }
        }
        __syncthreads();

        for (int i = w8; i < NT; i += 8) {
            float v0 = shc[i * SROW + lane];
            float v1 = (lane + 32 < NT) ? shc[i * SROW + lane + 32] : -1e30f;
            float mx = fmaxf(v0, v1);
            #pragma unroll
            for (int off = 16; off; off >>= 1)
                mx = fmaxf(mx, __shfl_xor_sync(0xffffffffu, mx, off));
            float e0 = __expf(v0 - mx);
            float e1 = (lane + 32 < NT) ? __expf(v1 - mx) : 0.0f;
            float sum = e0 + e1;
            #pragma unroll
            for (int off = 16; off; off >>= 1)
                sum += __shfl_xor_sync(0xffffffffu, sum, off);
            float inv = 1.0f / sum;
            shc[i * SROW + lane] = e0 * inv;
            if (lane + 32 < NT) shc[i * SROW + lane + 32] = e1 * inv;
        }
        __syncthreads();

        {
            const int vb = kb + lane;
            for (int ig = w8; ig < 13; ig += 8) {
                int i0 = ig * 4;
                float acc2[4] = {0.f, 0.f, 0.f, 0.f};
                #pragma unroll 4
                for (int j = 0; j < 48; j += 4) {
                    float4 p0 = *(const float4*)(shc + (i0 + 0) * SROW + j);
                    float4 p1 = *(const float4*)(shc + (i0 + 1) * SROW + j);
                    float4 p2 = *(const float4*)(shc + (i0 + 2) * SROW + j);
                    float4 p3 = *(const float4*)(shc + (i0 + 3) * SROW + j);
                    #pragma unroll
                    for (int jj = 0; jj < 4; jj++) {
                        float vv = vs[(j + jj) * CPAD + vb];
                        acc2[0] += ((const float*)&p0)[jj] * vv;
                        acc2[1] += ((const float*)&p1)[jj] * vv;
                        acc2[2] += ((const float*)&p2)[jj] * vv;
                        acc2[3] += ((const float*)&p3)[jj] * vv;
                    }
                }
                {
                    float vv = vs[48 * CPAD + vb];
                    acc2[0] += shc[(i0 + 0) * SROW + 48] * vv;
                    acc2[1] += shc[(i0 + 1) * SROW + 48] * vv;
                    acc2[2] += shc[(i0 + 2) * SROW + 48] * vv;
                    acc2[3] += shc[(i0 + 3) * SROW + 48] * vv;
                }
                #pragma unroll
                for (int ii = 0; ii < 4; ii++) {
                    if (i0 + ii < NT) {
                        __nv_bfloat16 hi, lo; bf16_split(acc2[ii], hi, lo);
                        int off = (i0 + ii) * XST + kb + lane;
                        aoim[off] = hi;
                        aoim[64 * XST + off] = lo;
                    }
                }
            }
        }
        __syncthreads();
    }
}

// ============================================================================
// Kernel 3: proj GEMM — M=64, 512 thr, 2 CTAs/SM, 3 stages of 64 oc (full K)
// smem: Ah 25600 | Al 25600 | Wh 25600 | Wl 25600 = 102400; ds overlays A
// ============================================================================
__global__ __launch_bounds__(512, 2)
void proj_kernel(const float* __restrict__ projB, float* __restrict__ out)
{
    extern __shared__ char smem[];
    float* ds = (float*)smem;    // overlays A after MMAs complete
    const uint32_t sb = smem_u32(smem);
    const int tid = threadIdx.x, lane = tid & 31, warp = tid >> 5;
    const int win = blockIdx.x;
    const int mw = warp & 3, nw = warp >> 2;

    // linear copy of both ao split images
    {
        const uint4* s = (const uint4*)(g_ao + (size_t)win * 2 * 64 * XST);
        uint4* d = (uint4*)smem;
        for (int i = tid; i < 3200; i += 512) d[i] = s[i];
    }
    __syncthreads();

    const uint32_t aoffh = sb + (uint32_t)(mw * 16 + (lane & 15)) * 400 + (lane >> 4) * 16;
    const uint32_t aoffl = aoffh + 25600;
    const uint32_t boffh = sb + 51200
        + (uint32_t)(nw * 16 + (lane & 7) + ((lane >> 4) << 3)) * 400 + ((lane >> 3) & 1) * 16;
    const uint32_t boffl = boffh + 25600;

    float acc[3][2][4];   // [stage][nt][e] — all 192 cols in regs
    #pragma unroll
    for (int s = 0; s < 3; s++)
        #pragma unroll
        for (int b = 0; b < 2; b++)
            #pragma unroll
            for (int e = 0; e < 4; e++) acc[s][b][e] = 0.f;

    for (int s = 0; s < 3; s++) {
        // stage 64 oc rows (hi+lo): 2 x 1536 uint4
        for (int i = tid; i < 3072; i += 512) {
            int split = i >= 1536, j = i - split * 1536;
            int r = j / 24, p = j - r * 24;
            __nv_bfloat16* dst = (__nv_bfloat16*)(smem + 51200 + split * 25600);
            ((uint4*)(dst + r * XST))[p] =
                ((const uint4*)(g_projw + split * (192 * 192) + (s * 64 + r) * 192))[p];
        }
        __syncthreads();

        #pragma unroll 2
        for (int k = 0; k < 12; k++) {
            uint32_t ah[4], al[4], b4h[4], b4l[4];
            LDSM4(ah, aoffh + k * 32);
            LDSM4(al, aoffl + k * 32);
            LDSM4(b4h, boffh + k * 32);
            LDSM4(b4l, boffl + k * 32);
            MMA_BF16_R(acc[s][0], ah, b4h[0], b4h[1]);
            MMA_BF16_R(acc[s][1], ah, b4h[2], b4h[3]);
            MMA_BF16_R(acc[s][0], ah, b4l[0], b4l[1]);
            MMA_BF16_R(acc[s][1], ah, b4l[2], b4l[3]);
            MMA_BF16_R(acc[s][0], al, b4h[0], b4h[1]);
            MMA_BF16_R(acc[s][1], al, b4h[2], b4h[3]);
        }
        __syncthreads();
    }

    // write accums into ds[c][tok] (+bias); ds overlays A region (A dead now)
    {
        const int g = lane >> 2, c2 = (lane & 3) * 2;
        #pragma unroll
        for (int s = 0; s < 3; s++)
            #pragma unroll
            for (int nt = 0; nt < 2; nt++) {
                int col = s * 64 + nw * 16 + nt * 8 + c2;
                float b0 = projB[col], b1 = projB[col + 1];
                #pragma unroll
                for (int rr = 0; rr < 2; rr++) {
                    int row = mw * 16 + g + rr * 8;
                    if (row < NT) {
                        ds[col * 50 + row]       = acc[s][nt][rr * 2 + 0] + b0;
                        ds[(col + 1) * 50 + row] = acc[s][nt][rr * 2 + 1] + b1;
                    }
                }
            }
    }
    __syncthreads();

    // scatter with reverse shift (coalesced along w)
    const int wy = win >> 6, wx = win & 63;
    for (int idx = tid; idx < CCH * NT; idx += 512) {
        int c = idx / NT, t = idx - c * NT;
        int r = t / 7, cc = t - r * 7;
        int h = wy * 7 + r + 3; if (h >= HDIM) h -= HDIM;
        int w = wx * 7 + cc + 3; if (w >= HDIM) w -= HDIM;
        out[c * HWSZ + h * HDIM + w] = ds[c * 50 + t];
    }
}

// ============================================================================
extern "C" void kernel_launch(void* const* d_in, const int* in_sizes, int n_in,
                              void* d_out, int out_size) {
    const float* x     = (const float*)d_in[0];
    const float* qkvW  = (const float*)d_in[1];
    const float* qkvB  = (const float*)d_in[2];
    const float* projW = (const float*)d_in[3];
    const float* projB = (const float*)d_in[4];
    const float* table = (const float*)d_in[5];
    float* out = (float*)d_out;

    cudaFuncSetAttribute(qkv_kernel,  cudaFuncAttributeMaxDynamicSharedMemorySize, GEMM_SMEM);
    cudaFuncSetAttribute(proj_kernel, cudaFuncAttributeMaxDynamicSharedMemorySize, GEMM_SMEM);
    cudaFuncSetAttribute(attn_kernel, cudaFuncAttributeMaxDynamicSharedMemorySize, ATTN_FLOATS * 4);

    prep_kernel<<<576, 256>>>(qkvW, projW);
    qkv_kernel<<<NWIN, 512, GEMM_SMEM>>>(x, qkvB);
    attn_kernel<<<NWIN, 512, ATTN_FLOATS * 4>>>(table);
    proj_kernel<<<NWIN, 512, GEMM_SMEM>>>(projB, out);
}

// round 14
// speedup vs baseline: 1.1839x; 1.1839x over previous
#include <cuda_runtime.h>
#include <cuda_bf16.h>
#include <cuda_fp16.h>
#include <cstdint>

#define NWIN  4096
#define NPAIR 2048
#define CCH   192
#define HDIM  448
#define HWSZ  (448*448)
#define NHEAD 6
#define HD    32
#define NT    49
#define CPAD  196
#define SROW  52
#define SCOFF 2816
#define XST   200      // fp16 row stride for mma tiles (400B: conflict-free ldmatrix)

// ---- device scratch ----
__device__ __align__(16) float g_q[(size_t)NWIN * NT * CCH];
__device__ __align__(16) float g_k[(size_t)NWIN * NT * CCH];
__device__ __align__(16) float g_v[(size_t)NWIN * NT * CCH];
__device__ __align__(16) __half g_qkvw[576 * 192];            // fp16 single
__device__ __align__(16) __half g_projw[192 * 192];           // fp16 single
__device__ __align__(16) __half g_ao[(size_t)NPAIR * 2 * 128 * XST]; // [pair][split][row][c]

// ---- helpers ----
__device__ __forceinline__ uint32_t smem_u32(const void* p) {
    uint32_t a;
    asm("{ .reg .u64 t; cvta.to.shared.u64 t, %1; cvt.u32.u64 %0, t; }" : "=r"(a) : "l"(p));
    return a;
}
#define LDSM4(r, a) asm volatile("ldmatrix.sync.aligned.m8n8.x4.shared.b16 {%0,%1,%2,%3}, [%4];" \
    : "=r"((r)[0]), "=r"((r)[1]), "=r"((r)[2]), "=r"((r)[3]) : "r"(a))
#define LDSM2(r, a) asm volatile("ldmatrix.sync.aligned.m8n8.x2.shared.b16 {%0,%1}, [%2];" \
    : "=r"((r)[0]), "=r"((r)[1]) : "r"(a))
#define MMA_F16(d, A, B) asm volatile( \
    "mma.sync.aligned.m16n8k16.row.col.f32.f16.f16.f32 " \
    "{%0,%1,%2,%3}, {%4,%5,%6,%7}, {%8,%9}, {%0,%1,%2,%3};" \
    : "+f"((d)[0]), "+f"((d)[1]), "+f"((d)[2]), "+f"((d)[3]) \
    : "r"((A)[0]), "r"((A)[1]), "r"((A)[2]), "r"((A)[3]), "r"((B)[0]), "r"((B)[1]))

__device__ __forceinline__ void f16_split(float v, __half& hi, __half& lo) {
    hi = __float2half(v);
    lo = __float2half(v - __half2float(hi));
}

// ============================================================================
// Kernel 0: weight prep (fp32 -> fp16 single, dense row-major)
// ============================================================================
__global__ void prep_kernel(const float* __restrict__ qkvW, const float* __restrict__ projW) {
    int i = blockIdx.x * blockDim.x + threadIdx.x;
    if (i < 576 * 192) {
        g_qkvw[i] = __float2half(qkvW[i]);
    } else {
        i -= 576 * 192;
        if (i < 192 * 192) g_projw[i] = __float2half(projW[i]);
    }
}

// ============================================================================
// Kernel 1: QKV GEMM (mma.sync fp16 2-product split), M=128 = 2 windows
// smem bytes: Xh 51200 | Xl 51200 | W 38400 = 140800
// ============================================================================
#define QKV_SMEM 140800

__global__ __launch_bounds__(512, 1)
void qkv_kernel(const float* __restrict__ x, const float* __restrict__ qkvB)
{
    extern __shared__ char smem[];
    __half* Xh = (__half*)smem;
    __half* Xl = (__half*)(smem + 51200);
    __half* Ws = (__half*)(smem + 102400);
    const uint32_t sb = smem_u32(smem);
    const int tid = threadIdx.x, lane = tid & 31, warp = tid >> 5;
    const int pair = blockIdx.x;
    const int mw = warp & 3, nw = warp >> 2;

    // gather 2 shifted windows, fp16-split
    for (int idx = tid; idx < 2 * NT * CCH; idx += 512) {
        int wl_ = idx / (NT * CCH), rem = idx - wl_ * NT * CCH;
        int c = rem / NT, t = rem - c * NT;
        int win = pair * 2 + wl_, wy = win >> 6, wx = win & 63;
        int r = t / 7, cc = t - r * 7;
        int h = wy * 7 + r + 3; if (h >= HDIM) h -= HDIM;
        int w = wx * 7 + cc + 3; if (w >= HDIM) w -= HDIM;
        __half hi, lo; f16_split(x[c * HWSZ + h * HDIM + w], hi, lo);
        int off = (wl_ * 64 + t) * XST + c;
        Xh[off] = hi; Xl[off] = lo;
    }
    // zero-pad rows 49..63, 113..127
    for (int idx = tid; idx < 30 * CCH; idx += 512) {
        int pr = idx / CCH, c = idx - pr * CCH;
        int row = (pr < 15) ? (49 + pr) : (98 + pr);
        int off = row * XST + c;
        Xh[off] = __float2half(0.f); Xl[off] = __float2half(0.f);
    }
    __syncthreads();

    // ldmatrix base offsets (bytes)
    const uint32_t aoffh = sb +          (uint32_t)(mw * 32 + (lane & 15)) * (XST * 2) + (lane >> 4) * 16;
    const uint32_t aoffl = aoffh + 51200;
    const uint32_t boff  = sb + 102400 + (uint32_t)(nw * 24 + (lane & 7)) * (XST * 2) + ((lane >> 3) & 1) * 16;

    for (int s = 0; s < 6; s++) {
        // stage 96 output rows of weights (fp16 single): 96 x 24 uint4
        for (int i = tid; i < 2304; i += 512) {
            int r = i / 24, p = i - r * 24;
            ((uint4*)(Ws + r * XST))[p] =
                ((const uint4*)(g_qkvw + (s * 96 + r) * 192))[p];
        }
        __syncthreads();

        float acc[2][3][4];
        #pragma unroll
        for (int a = 0; a < 2; a++)
            #pragma unroll
            for (int b = 0; b < 3; b++)
                #pragma unroll
                for (int e = 0; e < 4; e++) acc[a][b][e] = 0.f;

        #pragma unroll 2
        for (int k = 0; k < 12; k++) {
            uint32_t ah[2][4], al[2][4], bh[3][2];
            #pragma unroll
            for (int mt = 0; mt < 2; mt++) {
                LDSM4(ah[mt], aoffh + mt * 16 * (XST * 2) + k * 32);
                LDSM4(al[mt], aoffl + mt * 16 * (XST * 2) + k * 32);
            }
            #pragma unroll
            for (int nt = 0; nt < 3; nt++)
                LDSM2(bh[nt], boff + nt * 8 * (XST * 2) + k * 32);
            #pragma unroll
            for (int mt = 0; mt < 2; mt++)
                #pragma unroll
                for (int nt = 0; nt < 3; nt++)
                    MMA_F16(acc[mt][nt], ah[mt], bh[nt]);
            #pragma unroll
            for (int mt = 0; mt < 2; mt++)
                #pragma unroll
                for (int nt = 0; nt < 3; nt++)
                    MMA_F16(acc[mt][nt], al[mt], bh[nt]);
        }

        // epilogue: fp32 scratch with bias (+ q scale)
        const int g = lane >> 2, c2 = (lane & 3) * 2;
        #pragma unroll
        for (int mt = 0; mt < 2; mt++)
            #pragma unroll
            for (int nt = 0; nt < 3; nt++) {
                int col = s * 96 + nw * 24 + nt * 8 + c2;
                int buf = col / 192, ch = col - buf * 192;
                float scl = (buf == 0) ? 0.17677669529663687f : 1.0f;
                float* base = (buf == 0) ? g_q : (buf == 1) ? g_k : g_v;
                float b0 = qkvB[col], b1 = qkvB[col + 1];
                #pragma unroll
                for (int rr = 0; rr < 2; rr++) {
                    int row = mw * 32 + mt * 16 + g + rr * 8;
                    int wl_ = row >> 6, t = row & 63;
                    if (t < NT) {
                        float2 o;
                        o.x = (acc[mt][nt][rr * 2 + 0] + b0) * scl;
                        o.y = (acc[mt][nt][rr * 2 + 1] + b1) * scl;
                        *(float2*)(base + ((size_t)(pair * 2 + wl_) * NT + t) * CCH + ch) = o;
                    }
                }
            }
        __syncthreads();
    }
}

// ============================================================================
// Kernel 2: attention (per window), writes ao as fp16 splits (row-major)
// ============================================================================
constexpr int ATTN_FLOATS = 3 * NT * CPAD + 2 * SCOFF + 64;

__global__ __launch_bounds__(512, 1)
void attn_kernel(const float* __restrict__ table)
{
    extern __shared__ float smf[];
    float* qs = smf;
    float* ks = qs + NT * CPAD;
    float* vs = ks + NT * CPAD;
    float* sc = vs + NT * CPAD;
    int*   mreg = (int*)(sc + 2 * SCOFF);

    const int tid  = threadIdx.x;
    const int lane = tid & 31;
    const int warp = tid >> 5;
    const int w8   = warp & 7;
    const int half = warp >> 3;
    const int win = blockIdx.x;
    const int wy = win >> 6, wx = win & 63;

    if (tid < NT) {
        int r = tid / 7, cc = tid - (tid / 7) * 7;
        int hs = wy * 7 + r, ws = wx * 7 + cc;
        int rb = (hs >= 441) + (hs >= 445);
        int cb = (ws >= 441) + (ws >= 445);
        mreg[tid] = rb * 3 + cb;
    }
    {
        const float4* gq = (const float4*)(g_q + (size_t)win * NT * CCH);
        const float4* gk = (const float4*)(g_k + (size_t)win * NT * CCH);
        const float4* gv = (const float4*)(g_v + (size_t)win * NT * CCH);
        for (int i4 = tid; i4 < NT * 48; i4 += 512) {
            int t = i4 / 48, c4 = i4 - t * 48;
            ((float4*)(qs + t * CPAD))[c4] = gq[i4];
            ((float4*)(ks + t * CPAD))[c4] = gk[i4];
            ((float4*)(vs + t * CPAD))[c4] = gv[i4];
        }
    }
    __syncthreads();

    __half* aoim = g_ao + (size_t)(win >> 1) * 2 * 128 * XST;
    const int rowbase = (win & 1) * 64;

    for (int hp = 0; hp < 3; hp++) {
        const int h  = hp * 2 + half;
        const int kb = h * HD;
        float* shc = sc + half * SCOFF;

        for (int ig = w8; ig < 13; ig += 8) {
            int i0 = ig * 4;
            float a2[4][2] = {{0,0},{0,0},{0,0},{0,0}};
            const int j2 = lane + 32;
            const bool j2v = (j2 < NT);
            #pragma unroll
            for (int d = 0; d < HD; d += 4) {
                float4 k0 = *(const float4*)(ks + lane * CPAD + kb + d);
                float4 k1 = make_float4(0.f, 0.f, 0.f, 0.f);
                if (j2v) k1 = *(const float4*)(ks + j2 * CPAD + kb + d);
                #pragma unroll
                for (int ii = 0; ii < 4; ii++) {
                    const float4 q4 = *(const float4*)(qs + (i0 + ii) * CPAD + kb + d);
                    a2[ii][0] += q4.x*k0.x + q4.y*k0.y + q4.z*k0.z + q4.w*k0.w;
                    a2[ii][1] += q4.x*k1.x + q4.y*k1.y + q4.z*k1.z + q4.w*k1.w;
                }
            }
            #pragma unroll
            for (int ii = 0; ii < 4; ii++) {
                int i = i0 + ii;
                if (i >= NT) break;
                int ri = i / 7, ci = i - ri * 7;
                int mi = mreg[i];
                #pragma unroll
                for (int jj = 0; jj < 2; jj++) {
                    int j = lane + jj * 32;
                    if (j >= NT) continue;
                    int rj = j / 7, cj = j - rj * 7;
                    int rel = (ri - rj) + (ci - cj);
                    if (rel < 0) rel += 169;
                    float bi = table[rel * NHEAD + h];
                    float msk = (mi == mreg[j]) ? 0.0f : -100.0f;
                    shc[i * SROW + j] = a2[ii][jj] + bi + msk;
                }
            }
        }
        __syncthreads();

        for (int i = w8; i < NT; i += 8) {
            float v0 = shc[i * SROW + lane];
            float v1 = (lane + 32 < NT) ? shc[i * SROW + lane + 32] : -1e30f;
            float mx = fmaxf(v0, v1);
            #pragma unroll
            for (int off = 16; off; off >>= 1)
                mx = fmaxf(mx, __shfl_xor_sync(0xffffffffu, mx, off));
            float e0 = __expf(v0 - mx);
            float e1 = (lane + 32 < NT) ? __expf(v1 - mx) : 0.0f;
            float sum = e0 + e1;
            #pragma unroll
            for (int off = 16; off; off >>= 1)
                sum += __shfl_xor_sync(0xffffffffu, sum, off);
            float inv = 1.0f / sum;
            shc[i * SROW + lane] = e0 * inv;
            if (lane + 32 < NT) shc[i * SROW + lane + 32] = e1 * inv;
        }
        __syncthreads();

        {
            const int vb = kb + lane;
            for (int ig = w8; ig < 13; ig += 8) {
                int i0 = ig * 4;
                float acc2[4] = {0.f, 0.f, 0.f, 0.f};
                #pragma unroll 4
                for (int j = 0; j < 48; j += 4) {
                    float4 p0 = *(const float4*)(shc + (i0 + 0) * SROW + j);
                    float4 p1 = *(const float4*)(shc + (i0 + 1) * SROW + j);
                    float4 p2 = *(const float4*)(shc + (i0 + 2) * SROW + j);
                    float4 p3 = *(const float4*)(shc + (i0 + 3) * SROW + j);
                    #pragma unroll
                    for (int jj = 0; jj < 4; jj++) {
                        float vv = vs[(j + jj) * CPAD + vb];
                        acc2[0] += ((const float*)&p0)[jj] * vv;
                        acc2[1] += ((const float*)&p1)[jj] * vv;
                        acc2[2] += ((const float*)&p2)[jj] * vv;
                        acc2[3] += ((const float*)&p3)[jj] * vv;
                    }
                }
                {
                    float vv = vs[48 * CPAD + vb];
                    acc2[0] += shc[(i0 + 0) * SROW + 48] * vv;
                    acc2[1] += shc[(i0 + 1) * SROW + 48] * vv;
                    acc2[2] += shc[(i0 + 2) * SROW + 48] * vv;
                    acc2[3] += shc[(i0 + 3) * SROW + 48] * vv;
                }
                #pragma unroll
                for (int ii = 0; ii < 4; ii++) {
                    if (i0 + ii < NT) {
                        __half hi, lo; f16_split(acc2[ii], hi, lo);
                        int off = (rowbase + i0 + ii) * XST + kb + lane;
                        aoim[off] = hi;
                        aoim[128 * XST + off] = lo;
                    }
                }
            }
        }
        __syncthreads();
    }
}

// ============================================================================
// Kernel 3: proj GEMM (mma.sync fp16 2-product) + shifted scatter
// smem: Ah 51200 | Al 51200 | W 38400 = 140800 ; ds overlays Ah/Al
// ============================================================================
#define PROJ_SMEM 140800

__global__ __launch_bounds__(512, 1)
void proj_kernel(const float* __restrict__ projB, float* __restrict__ out)
{
    extern __shared__ char smem[];
    __half* Ws = (__half*)(smem + 102400);
    float* ds = (float*)smem;
    const uint32_t sb = smem_u32(smem);
    const int tid = threadIdx.x, lane = tid & 31, warp = tid >> 5;
    const int pair = blockIdx.x;
    const int mw = warp & 3, nw = warp >> 2;

    // linear copy of both ao split images (already padded/row-major)
    {
        const uint4* s = (const uint4*)(g_ao + (size_t)pair * 2 * 128 * XST);
        uint4* d = (uint4*)smem;
        for (int i = tid; i < 6400; i += 512) d[i] = s[i];
    }
    __syncthreads();

    const uint32_t aoffh = sb +          (uint32_t)(mw * 32 + (lane & 15)) * (XST * 2) + (lane >> 4) * 16;
    const uint32_t aoffl = aoffh + 51200;
    const uint32_t boff  = sb + 102400 + (uint32_t)(nw * 24 + (lane & 7)) * (XST * 2) + ((lane >> 3) & 1) * 16;

    float acc[2][2][3][4];   // [stage][mt][nt][e]
    #pragma unroll
    for (int s = 0; s < 2; s++)
        #pragma unroll
        for (int a = 0; a < 2; a++)
            #pragma unroll
            for (int b = 0; b < 3; b++)
                #pragma unroll
                for (int e = 0; e < 4; e++) acc[s][a][b][e] = 0.f;

    for (int s = 0; s < 2; s++) {
        for (int i = tid; i < 2304; i += 512) {
            int r = i / 24, p = i - r * 24;
            ((uint4*)(Ws + r * XST))[p] =
                ((const uint4*)(g_projw + (s * 96 + r) * 192))[p];
        }
        __syncthreads();

        #pragma unroll 2
        for (int k = 0; k < 12; k++) {
            uint32_t ah[2][4], al[2][4], bh[3][2];
            #pragma unroll
            for (int mt = 0; mt < 2; mt++) {
                LDSM4(ah[mt], aoffh + mt * 16 * (XST * 2) + k * 32);
                LDSM4(al[mt], aoffl + mt * 16 * (XST * 2) + k * 32);
            }
            #pragma unroll
            for (int nt = 0; nt < 3; nt++)
                LDSM2(bh[nt], boff + nt * 8 * (XST * 2) + k * 32);
            #pragma unroll
            for (int mt = 0; mt < 2; mt++)
                #pragma unroll
                for (int nt = 0; nt < 3; nt++)
                    MMA_F16(acc[s][mt][nt], ah[mt], bh[nt]);
            #pragma unroll
            for (int mt = 0; mt < 2; mt++)
                #pragma unroll
                for (int nt = 0; nt < 3; nt++)
                    MMA_F16(acc[s][mt][nt], al[mt], bh[nt]);
        }
        __syncthreads();
    }

    // write accums into ds[c][tok2] (+bias); ds overlays A region (A dead now)
    {
        const int g = lane >> 2, c2 = (lane & 3) * 2;
        #pragma unroll
        for (int s = 0; s < 2; s++)
            #pragma unroll
            for (int mt = 0; mt < 2; mt++)
                #pragma unroll
                for (int nt = 0; nt < 3; nt++) {
                    int col = s * 96 + nw * 24 + nt * 8 + c2;
                    float b0 = projB[col], b1 = projB[col + 1];
                    #pragma unroll
                    for (int rr = 0; rr < 2; rr++) {
                        int row = mw * 32 + mt * 16 + g + rr * 8;
                        int wl_ = row >> 6, t = row & 63;
                        if (t < NT) {
                            int tt = wl_ * 49 + t;
                            ds[col * 100 + tt]       = acc[s][mt][nt][rr * 2 + 0] + b0;
                            ds[(col + 1) * 100 + tt] = acc[s][mt][nt][rr * 2 + 1] + b1;
                        }
                    }
                }
    }
    __syncthreads();

    // scatter with reverse shift (coalesced along w)
    for (int idx = tid; idx < CCH * 98; idx += 512) {
        int c = idx / 98, tt = idx - c * 98;
        int wl_ = tt / 49, t = tt - wl_ * 49;
        int win = pair * 2 + wl_, wy = win >> 6, wx = win & 63;
        int r = t / 7, cc = t - r * 7;
        int h = wy * 7 + r + 3; if (h >= HDIM) h -= HDIM;
        int w = wx * 7 + cc + 3; if (w >= HDIM) w -= HDIM;
        out[c * HWSZ + h * HDIM + w] = ds[c * 100 + tt];
    }
}

// ============================================================================
extern "C" void kernel_launch(void* const* d_in, const int* in_sizes, int n_in,
                              void* d_out, int out_size) {
    const float* x     = (const float*)d_in[0];
    const float* qkvW  = (const float*)d_in[1];
    const float* qkvB  = (const float*)d_in[2];
    const float* projW = (const float*)d_in[3];
    const float* projB = (const float*)d_in[4];
    const float* table = (const float*)d_in[5];
    float* out = (float*)d_out;

    cudaFuncSetAttribute(qkv_kernel,  cudaFuncAttributeMaxDynamicSharedMemorySize, QKV_SMEM);
    cudaFuncSetAttribute(proj_kernel, cudaFuncAttributeMaxDynamicSharedMemorySize, PROJ_SMEM);
    cudaFuncSetAttribute(attn_kernel, cudaFuncAttributeMaxDynamicSharedMemorySize, ATTN_FLOATS * 4);

    prep_kernel<<<576, 256>>>(qkvW, projW);
    qkv_kernel<<<NPAIR, 512, QKV_SMEM>>>(x, qkvB);
    attn_kernel<<<NWIN, 512, ATTN_FLOATS * 4>>>(table);
    proj_kernel<<<NPAIR, 512, PROJ_SMEM>>>(projB, out);
}

// round 15
// speedup vs baseline: 1.2836x; 1.0842x over previous
#include <cuda_runtime.h>
#include <cuda_fp16.h>
#include <cstdint>

#define NWIN  4096
#define NPAIR 2048
#define CCH   192
#define HDIM  448
#define HWSZ  (448*448)
#define NHEAD 6
#define HD    32
#define NT    49
#define CPAD  196
#define SROW  52
#define SCH   2720     // per-head score buffer (floats; covers speculative reads to row 51)
#define XST   200      // fp16 row stride for mma tiles (400B: conflict-free ldmatrix)

// ---- device scratch ----
__device__ __align__(16) float g_q[(size_t)NWIN * NT * CCH];
__device__ __align__(16) float g_k[(size_t)NWIN * NT * CCH];
__device__ __align__(16) float g_v[(size_t)NWIN * NT * CCH];
__device__ __align__(16) __half g_qkvw[576 * 192];
__device__ __align__(16) __half g_projw[192 * 192];
__device__ __align__(16) __half g_ao[(size_t)NPAIR * 2 * 128 * XST]; // [pair][split][row][c]

// ---- helpers ----
__device__ __forceinline__ uint32_t smem_u32(const void* p) {
    uint32_t a;
    asm("{ .reg .u64 t; cvta.to.shared.u64 t, %1; cvt.u32.u64 %0, t; }" : "=r"(a) : "l"(p));
    return a;
}
#define LDSM4(r, a) asm volatile("ldmatrix.sync.aligned.m8n8.x4.shared.b16 {%0,%1,%2,%3}, [%4];" \
    : "=r"((r)[0]), "=r"((r)[1]), "=r"((r)[2]), "=r"((r)[3]) : "r"(a))
#define LDSM2(r, a) asm volatile("ldmatrix.sync.aligned.m8n8.x2.shared.b16 {%0,%1}, [%2];" \
    : "=r"((r)[0]), "=r"((r)[1]) : "r"(a))
#define MMA_F16(d, A, B) asm volatile( \
    "mma.sync.aligned.m16n8k16.row.col.f32.f16.f16.f32 " \
    "{%0,%1,%2,%3}, {%4,%5,%6,%7}, {%8,%9}, {%0,%1,%2,%3};" \
    : "+f"((d)[0]), "+f"((d)[1]), "+f"((d)[2]), "+f"((d)[3]) \
    : "r"((A)[0]), "r"((A)[1]), "r"((A)[2]), "r"((A)[3]), "r"((B)[0]), "r"((B)[1]))

__device__ __forceinline__ void f16_split(float v, __half& hi, __half& lo) {
    hi = __float2half(v);
    lo = __float2half(v - __half2float(hi));
}

// ============================================================================
// Kernel 0: weight prep (fp32 -> fp16, dense row-major)
// ============================================================================
__global__ void prep_kernel(const float* __restrict__ qkvW, const float* __restrict__ projW) {
    int i = blockIdx.x * blockDim.x + threadIdx.x;
    if (i < 576 * 192) {
        g_qkvw[i] = __float2half(qkvW[i]);
    } else {
        i -= 576 * 192;
        if (i < 192 * 192) g_projw[i] = __float2half(projW[i]);
    }
}

// ============================================================================
// Kernel 1: QKV GEMM — M=128 (2 windows), 3 stages of 192 oc, fp16 2-product
// smem: Xh 51200 | Xl 51200 | W 76800 = 179200
// ============================================================================
#define QKV_SMEM 179200

__global__ __launch_bounds__(512, 1)
void qkv_kernel(const float* __restrict__ x, const float* __restrict__ qkvB)
{
    extern __shared__ char smem[];
    __half* Xh = (__half*)smem;
    __half* Xl = (__half*)(smem + 51200);
    __half* Ws = (__half*)(smem + 102400);
    const uint32_t sb = smem_u32(smem);
    const int tid = threadIdx.x, lane = tid & 31, warp = tid >> 5;
    const int pair = blockIdx.x;
    const int mw = warp & 3, nw = warp >> 2;

    // gather 2 shifted windows, fp16-split
    for (int idx = tid; idx < 2 * NT * CCH; idx += 512) {
        int wl_ = idx / (NT * CCH), rem = idx - wl_ * NT * CCH;
        int c = rem / NT, t = rem - c * NT;
        int win = pair * 2 + wl_, wy = win >> 6, wx = win & 63;
        int r = t / 7, cc = t - r * 7;
        int h = wy * 7 + r + 3; if (h >= HDIM) h -= HDIM;
        int w = wx * 7 + cc + 3; if (w >= HDIM) w -= HDIM;
        __half hi, lo; f16_split(x[c * HWSZ + h * HDIM + w], hi, lo);
        int off = (wl_ * 64 + t) * XST + c;
        Xh[off] = hi; Xl[off] = lo;
    }
    for (int idx = tid; idx < 30 * CCH; idx += 512) {    // pad rows 49..63, 113..127
        int pr = idx / CCH, c = idx - pr * CCH;
        int row = (pr < 15) ? (49 + pr) : (98 + pr);
        int off = row * XST + c;
        Xh[off] = __float2half(0.f); Xl[off] = __float2half(0.f);
    }
    __syncthreads();

    const uint32_t aoffh = sb +          (uint32_t)(mw * 32 + (lane & 15)) * (XST * 2) + (lane >> 4) * 16;
    const uint32_t aoffl = aoffh + 51200;
    const uint32_t boff  = sb + 102400 + (uint32_t)(nw * 48 + (lane & 7)) * (XST * 2) + ((lane >> 3) & 1) * 16;

    for (int s = 0; s < 3; s++) {
        // stage 192 output rows of weights: 192 x 24 uint4
        for (int i = tid; i < 4608; i += 512) {
            int r = i / 24, p = i - r * 24;
            ((uint4*)(Ws + r * XST))[p] =
                ((const uint4*)(g_qkvw + (s * 192 + r) * 192))[p];
        }
        __syncthreads();

        float acc[2][6][4];
        #pragma unroll
        for (int a = 0; a < 2; a++)
            #pragma unroll
            for (int b = 0; b < 6; b++)
                #pragma unroll
                for (int e = 0; e < 4; e++) acc[a][b][e] = 0.f;

        #pragma unroll 2
        for (int k = 0; k < 12; k++) {
            uint32_t ah[2][4], al[2][4], bh[6][2];
            #pragma unroll
            for (int mt = 0; mt < 2; mt++) {
                LDSM4(ah[mt], aoffh + mt * 16 * (XST * 2) + k * 32);
                LDSM4(al[mt], aoffl + mt * 16 * (XST * 2) + k * 32);
            }
            #pragma unroll
            for (int nt = 0; nt < 6; nt++)
                LDSM2(bh[nt], boff + nt * 8 * (XST * 2) + k * 32);
            #pragma unroll
            for (int mt = 0; mt < 2; mt++)
                #pragma unroll
                for (int nt = 0; nt < 6; nt++)
                    MMA_F16(acc[mt][nt], ah[mt], bh[nt]);
            #pragma unroll
            for (int mt = 0; mt < 2; mt++)
                #pragma unroll
                for (int nt = 0; nt < 6; nt++)
                    MMA_F16(acc[mt][nt], al[mt], bh[nt]);
        }

        // epilogue: fp32 scratch with bias (+ q scale)
        const int g = lane >> 2, c2 = (lane & 3) * 2;
        #pragma unroll
        for (int mt = 0; mt < 2; mt++)
            #pragma unroll
            for (int nt = 0; nt < 6; nt++) {
                int col = s * 192 + nw * 48 + nt * 8 + c2;
                int buf = col / 192, ch = col - buf * 192;
                float scl = (buf == 0) ? 0.17677669529663687f : 1.0f;
                float* base = (buf == 0) ? g_q : (buf == 1) ? g_k : g_v;
                float b0 = qkvB[col], b1 = qkvB[col + 1];
                #pragma unroll
                for (int rr = 0; rr < 2; rr++) {
                    int row = mw * 32 + mt * 16 + g + rr * 8;
                    int wl_ = row >> 6, t = row & 63;
                    if (t < NT) {
                        float2 o;
                        o.x = (acc[mt][nt][rr * 2 + 0] + b0) * scl;
                        o.y = (acc[mt][nt][rr * 2 + 1] + b1) * scl;
                        *(float2*)(base + ((size_t)(pair * 2 + wl_) * NT + t) * CCH + ch) = o;
                    }
                }
            }
        __syncthreads();
    }
}

// ============================================================================
// Kernel 2: attention — all 6 heads per phase, 3 barriers
// smem floats: qs|ks|vs (28812) | sc 6*2720 (16320) | mreg
// ============================================================================
constexpr int ATTN_FLOATS = 3 * NT * CPAD + 6 * SCH + 64;

__global__ __launch_bounds__(512, 1)
void attn_kernel(const float* __restrict__ table)
{
    extern __shared__ float smf[];
    float* qs = smf;
    float* ks = qs + NT * CPAD;
    float* vs = ks + NT * CPAD;
    float* sc = vs + NT * CPAD;
    int*   mreg = (int*)(sc + 6 * SCH);

    const int tid  = threadIdx.x;
    const int lane = tid & 31;
    const int warp = tid >> 5;
    const int win = blockIdx.x;
    const int wy = win >> 6, wx = win & 63;

    if (tid < NT) {
        int r = tid / 7, cc = tid - (tid / 7) * 7;
        int hs = wy * 7 + r, ws = wx * 7 + cc;
        int rb = (hs >= 441) + (hs >= 445);
        int cb = (ws >= 441) + (ws >= 445);
        mreg[tid] = rb * 3 + cb;
    }
    {
        const float4* gq = (const float4*)(g_q + (size_t)win * NT * CCH);
        const float4* gk = (const float4*)(g_k + (size_t)win * NT * CCH);
        const float4* gv = (const float4*)(g_v + (size_t)win * NT * CCH);
        for (int i4 = tid; i4 < NT * 48; i4 += 512) {
            int t = i4 / 48, c4 = i4 - t * 48;
            ((float4*)(qs + t * CPAD))[c4] = gq[i4];
            ((float4*)(ks + t * CPAD))[c4] = gk[i4];
            ((float4*)(vs + t * CPAD))[c4] = gv[i4];
        }
    }
    __syncthreads();

    __half* aoim = g_ao + (size_t)(win >> 1) * 2 * 128 * XST;
    const int rowbase = (win & 1) * 64;

    // ---- Phase A: scores for all heads (78 warp-tasks) ----
    for (int task = warp; task < 78; task += 16) {
        const int h = task / 13, ig = task - h * 13;
        const int kb = h * HD;
        float* shc = sc + h * SCH;
        int i0 = ig * 4;
        float a2[4][2] = {{0,0},{0,0},{0,0},{0,0}};
        const int j2 = lane + 32;
        const bool j2v = (j2 < NT);
        #pragma unroll
        for (int d = 0; d < HD; d += 4) {
            float4 k0 = *(const float4*)(ks + lane * CPAD + kb + d);
            float4 k1 = make_float4(0.f, 0.f, 0.f, 0.f);
            if (j2v) k1 = *(const float4*)(ks + j2 * CPAD + kb + d);
            #pragma unroll
            for (int ii = 0; ii < 4; ii++) {
                const float4 q4 = *(const float4*)(qs + (i0 + ii) * CPAD + kb + d);
                a2[ii][0] += q4.x*k0.x + q4.y*k0.y + q4.z*k0.z + q4.w*k0.w;
                a2[ii][1] += q4.x*k1.x + q4.y*k1.y + q4.z*k1.z + q4.w*k1.w;
            }
        }
        #pragma unroll
        for (int ii = 0; ii < 4; ii++) {
            int i = i0 + ii;
            if (i >= NT) break;
            int ri = i / 7, ci = i - ri * 7;
            int mi = mreg[i];
            #pragma unroll
            for (int jj = 0; jj < 2; jj++) {
                int j = lane + jj * 32;
                if (j >= NT) continue;
                int rj = j / 7, cj = j - rj * 7;
                int rel = (ri - rj) + (ci - cj);
                if (rel < 0) rel += 169;
                float bi = table[rel * NHEAD + h];
                float msk = (mi == mreg[j]) ? 0.0f : -100.0f;
                shc[i * SROW + j] = a2[ii][jj] + bi + msk;
            }
        }
    }
    __syncthreads();

    // ---- Phase B: softmax for all heads (294 row-tasks) ----
    for (int task = warp; task < 294; task += 16) {
        const int h = task / 49, i = task - h * 49;
        float* shc = sc + h * SCH;
        float v0 = shc[i * SROW + lane];
        float v1 = (lane + 32 < NT) ? shc[i * SROW + lane + 32] : -1e30f;
        float mx = fmaxf(v0, v1);
        #pragma unroll
        for (int off = 16; off; off >>= 1)
            mx = fmaxf(mx, __shfl_xor_sync(0xffffffffu, mx, off));
        float e0 = __expf(v0 - mx);
        float e1 = (lane + 32 < NT) ? __expf(v1 - mx) : 0.0f;
        float sum = e0 + e1;
        #pragma unroll
        for (int off = 16; off; off >>= 1)
            sum += __shfl_xor_sync(0xffffffffu, sum, off);
        float inv = 1.0f / sum;
        shc[i * SROW + lane] = e0 * inv;
        if (lane + 32 < NT) shc[i * SROW + lane + 32] = e1 * inv;
    }
    __syncthreads();

    // ---- Phase C: P @ V for all heads (78 warp-tasks) ----
    for (int task = warp; task < 78; task += 16) {
        const int h = task / 13, ig = task - h * 13;
        const int kb = h * HD;
        float* shc = sc + h * SCH;
        const int vb = kb + lane;
        int i0 = ig * 4;
        float acc2[4] = {0.f, 0.f, 0.f, 0.f};
        #pragma unroll 4
        for (int j = 0; j < 48; j += 4) {
            float4 p0 = *(const float4*)(shc + (i0 + 0) * SROW + j);
            float4 p1 = *(const float4*)(shc + (i0 + 1) * SROW + j);
            float4 p2 = *(const float4*)(shc + (i0 + 2) * SROW + j);
            float4 p3 = *(const float4*)(shc + (i0 + 3) * SROW + j);
            #pragma unroll
            for (int jj = 0; jj < 4; jj++) {
                float vv = vs[(j + jj) * CPAD + vb];
                acc2[0] += ((const float*)&p0)[jj] * vv;
                acc2[1] += ((const float*)&p1)[jj] * vv;
                acc2[2] += ((const float*)&p2)[jj] * vv;
                acc2[3] += ((const float*)&p3)[jj] * vv;
            }
        }
        {
            float vv = vs[48 * CPAD + vb];
            acc2[0] += shc[(i0 + 0) * SROW + 48] * vv;
            acc2[1] += shc[(i0 + 1) * SROW + 48] * vv;
            acc2[2] += shc[(i0 + 2) * SROW + 48] * vv;
            acc2[3] += shc[(i0 + 3) * SROW + 48] * vv;
        }
        #pragma unroll
        for (int ii = 0; ii < 4; ii++) {
            if (i0 + ii < NT) {
                __half hi, lo; f16_split(acc2[ii], hi, lo);
                int off = (rowbase + i0 + ii) * XST + kb + lane;
                aoim[off] = hi;
                aoim[128 * XST + off] = lo;
            }
        }
    }
}

// ============================================================================
// Kernel 3: proj GEMM — single stage of all 192 oc + shifted scatter
// smem: Ah 51200 | Al 51200 | W 76800 = 179200 ; ds overlays Ah/Al
// ============================================================================
#define PROJ_SMEM 179200

__global__ __launch_bounds__(512, 1)
void proj_kernel(const float* __restrict__ projB, float* __restrict__ out)
{
    extern __shared__ char smem[];
    __half* Ws = (__half*)(smem + 102400);
    float* ds = (float*)smem;
    const uint32_t sb = smem_u32(smem);
    const int tid = threadIdx.x, lane = tid & 31, warp = tid >> 5;
    const int pair = blockIdx.x;
    const int mw = warp & 3, nw = warp >> 2;

    // copy both ao split images + stage all proj weights
    {
        const uint4* s = (const uint4*)(g_ao + (size_t)pair * 2 * 128 * XST);
        uint4* d = (uint4*)smem;
        for (int i = tid; i < 6400; i += 512) d[i] = s[i];
    }
    for (int i = tid; i < 4608; i += 512) {
        int r = i / 24, p = i - r * 24;
        ((uint4*)(Ws + r * XST))[p] = ((const uint4*)(g_projw + r * 192))[p];
    }
    __syncthreads();

    const uint32_t aoffh = sb +          (uint32_t)(mw * 32 + (lane & 15)) * (XST * 2) + (lane >> 4) * 16;
    const uint32_t aoffl = aoffh + 51200;
    const uint32_t boff  = sb + 102400 + (uint32_t)(nw * 48 + (lane & 7)) * (XST * 2) + ((lane >> 3) & 1) * 16;

    float acc[2][6][4];
    #pragma unroll
    for (int a = 0; a < 2; a++)
        #pragma unroll
        for (int b = 0; b < 6; b++)
            #pragma unroll
            for (int e = 0; e < 4; e++) acc[a][b][e] = 0.f;

    #pragma unroll 2
    for (int k = 0; k < 12; k++) {
        uint32_t ah[2][4], al[2][4], bh[6][2];
        #pragma unroll
        for (int mt = 0; mt < 2; mt++) {
            LDSM4(ah[mt], aoffh + mt * 16 * (XST * 2) + k * 32);
            LDSM4(al[mt], aoffl + mt * 16 * (XST * 2) + k * 32);
        }
        #pragma unroll
        for (int nt = 0; nt < 6; nt++)
            LDSM2(bh[nt], boff + nt * 8 * (XST * 2) + k * 32);
        #pragma unroll
        for (int mt = 0; mt < 2; mt++)
            #pragma unroll
            for (int nt = 0; nt < 6; nt++)
                MMA_F16(acc[mt][nt], ah[mt], bh[nt]);
        #pragma unroll
        for (int mt = 0; mt < 2; mt++)
            #pragma unroll
            for (int nt = 0; nt < 6; nt++)
                MMA_F16(acc[mt][nt], al[mt], bh[nt]);
    }
    __syncthreads();

    // write accums into ds[c][tok2] (+bias); ds overlays A region (A dead now)
    {
        const int g = lane >> 2, c2 = (lane & 3) * 2;
        #pragma unroll
        for (int mt = 0; mt < 2; mt++)
            #pragma unroll
            for (int nt = 0; nt < 6; nt++) {
                int col = nw * 48 + nt * 8 + c2;
                float b0 = projB[col], b1 = projB[col + 1];
                #pragma unroll
                for (int rr = 0; rr < 2; rr++) {
                    int row = mw * 32 + mt * 16 + g + rr * 8;
                    int wl_ = row >> 6, t = row & 63;
                    if (t < NT) {
                        int tt = wl_ * 49 + t;
                        ds[col * 100 + tt]       = acc[mt][nt][rr * 2 + 0] + b0;
                        ds[(col + 1) * 100 + tt] = acc[mt][nt][rr * 2 + 1] + b1;
                    }
                }
            }
    }
    __syncthreads();

    // scatter with reverse shift (coalesced along w)
    for (int idx = tid; idx < CCH * 98; idx += 512) {
        int c = idx / 98, tt = idx - c * 98;
        int wl_ = tt / 49, t = tt - wl_ * 49;
        int win = pair * 2 + wl_, wy = win >> 6, wx = win & 63;
        int r = t / 7, cc = t - r * 7;
        int h = wy * 7 + r + 3; if (h >= HDIM) h -= HDIM;
        int w = wx * 7 + cc + 3; if (w >= HDIM) w -= HDIM;
        out[c * HWSZ + h * HDIM + w] = ds[c * 100 + tt];
    }
}

// ============================================================================
extern "C" void kernel_launch(void* const* d_in, const int* in_sizes, int n_in,
                              void* d_out, int out_size) {
    const float* x     = (const float*)d_in[0];
    const float* qkvW  = (const float*)d_in[1];
    const float* qkvB  = (const float*)d_in[2];
    const float* projW = (const float*)d_in[3];
    const float* projB = (const float*)d_in[4];
    const float* table = (const float*)d_in[5];
    float* out = (float*)d_out;

    cudaFuncSetAttribute(qkv_kernel,  cudaFuncAttributeMaxDynamicSharedMemorySize, QKV_SMEM);
    cudaFuncSetAttribute(proj_kernel, cudaFuncAttributeMaxDynamicSharedMemorySize, PROJ_SMEM);
    cudaFuncSetAttribute(attn_kernel, cudaFuncAttributeMaxDynamicSharedMemorySize, ATTN_FLOATS * 4);

    prep_kernel<<<576, 256>>>(qkvW, projW);
    qkv_kernel<<<NPAIR, 512, QKV_SMEM>>>(x, qkvB);
    attn_kernel<<<NWIN, 512, ATTN_FLOATS * 4>>>(table);
    proj_kernel<<<NPAIR, 512, PROJ_SMEM>>>(projB, out);
}

// round 16
// speedup vs baseline: 1.4117x; 1.0998x over previous
#include <cuda_runtime.h>
#include <cuda_fp16.h>
#include <cstdint>

#define NWIN  4096
#define NPAIR 2048
#define CCH   192
#define HDIM  448
#define HWSZ  (448*448)
#define NHEAD 6
#define HD    32
#define NT    49
#define CPAD  196
#define SROW  52
#define SCH   2720     // per-head score buffer (floats)
#define XST   200      // fp16 row stride for mma tiles (400B)

// ---- device scratch ----
__device__ __align__(16) float g_q[(size_t)NWIN * NT * CCH];
__device__ __align__(16) float g_k[(size_t)NWIN * NT * CCH];
__device__ __align__(16) float g_v[(size_t)NWIN * NT * CCH];
__device__ __align__(16) __half g_qkvw[576 * 192];
__device__ __align__(16) __half g_projw[192 * 192];
__device__ __align__(16) __half g_ao[(size_t)NPAIR * 2 * 128 * XST]; // [pair][split][row][c]

// ---- helpers ----
__device__ __forceinline__ uint32_t smem_u32(const void* p) {
    uint32_t a;
    asm("{ .reg .u64 t; cvta.to.shared.u64 t, %1; cvt.u32.u64 %0, t; }" : "=r"(a) : "l"(p));
    return a;
}
#define LDSM4(r, a) asm volatile("ldmatrix.sync.aligned.m8n8.x4.shared.b16 {%0,%1,%2,%3}, [%4];" \
    : "=r"((r)[0]), "=r"((r)[1]), "=r"((r)[2]), "=r"((r)[3]) : "r"(a))
#define LDSM2(r, a) asm volatile("ldmatrix.sync.aligned.m8n8.x2.shared.b16 {%0,%1}, [%2];" \
    : "=r"((r)[0]), "=r"((r)[1]) : "r"(a))
#define MMA_F16(d, A, B) asm volatile( \
    "mma.sync.aligned.m16n8k16.row.col.f32.f16.f16.f32 " \
    "{%0,%1,%2,%3}, {%4,%5,%6,%7}, {%8,%9}, {%0,%1,%2,%3};" \
    : "+f"((d)[0]), "+f"((d)[1]), "+f"((d)[2]), "+f"((d)[3]) \
    : "r"((A)[0]), "r"((A)[1]), "r"((A)[2]), "r"((A)[3]), "r"((B)[0]), "r"((B)[1]))

#define CPA16(dst, src) asm volatile("cp.async.cg.shared.global [%0], [%1], 16;" \
    :: "r"(dst), "l"(__cvta_generic_to_global(src)) : "memory")
#define CPA_COMMIT() asm volatile("cp.async.commit_group;" ::: "memory")
#define CPA_WAIT(N)  asm volatile("cp.async.wait_group %0;" :: "n"(N) : "memory")

__device__ __forceinline__ void f16_split(float v, __half& hi, __half& lo) {
    hi = __float2half(v);
    lo = __float2half(v - __half2float(hi));
}

// ============================================================================
// Kernel 0: weight prep (fp32 -> fp16, dense row-major)
// ============================================================================
__global__ void prep_kernel(const float* __restrict__ qkvW, const float* __restrict__ projW) {
    int i = blockIdx.x * blockDim.x + threadIdx.x;
    if (i < 576 * 192) {
        g_qkvw[i] = __float2half(qkvW[i]);
    } else {
        i -= 576 * 192;
        if (i < 192 * 192) g_projw[i] = __float2half(projW[i]);
    }
}

// ============================================================================
// Kernel 1: QKV GEMM — M=128 (2 windows), 6 stages of 96 oc,
//           cp.async double-buffered weight staging
// smem: Xh 51200 | Xl 51200 | W0 38400 | W1 38400 = 179200
// ============================================================================
#define QKV_SMEM 179200

__global__ __launch_bounds__(512, 1)
void qkv_kernel(const float* __restrict__ x, const float* __restrict__ qkvB)
{
    extern __shared__ char smem[];
    __half* Xh = (__half*)smem;
    __half* Xl = (__half*)(smem + 51200);
    const uint32_t sb = smem_u32(smem);
    const int tid = threadIdx.x, lane = tid & 31, warp = tid >> 5;
    const int pair = blockIdx.x;
    const int mw = warp & 3, nw = warp >> 2;

    // stage weights for stage s into buffer buf (96 rows x 24 uint4)
    auto stageW = [&](int s, int buf) {
        const uint32_t dstb = sb + 102400 + (uint32_t)buf * 38400;
        const __half* src = g_qkvw + s * 96 * 192;
        for (int i = tid; i < 2304; i += 512) {
            int r = i / 24, p = i - r * 24;
            CPA16(dstb + (uint32_t)r * (XST * 2) + p * 16, (const char*)(src + r * 192) + p * 16);
        }
        CPA_COMMIT();
    };

    stageW(0, 0);   // prefetch stage 0 while we gather X

    // gather 2 shifted windows, fp16-split
    for (int idx = tid; idx < 2 * NT * CCH; idx += 512) {
        int wl_ = idx / (NT * CCH), rem = idx - wl_ * NT * CCH;
        int c = rem / NT, t = rem - c * NT;
        int win = pair * 2 + wl_, wy = win >> 6, wx = win & 63;
        int r = t / 7, cc = t - r * 7;
        int h = wy * 7 + r + 3; if (h >= HDIM) h -= HDIM;
        int w = wx * 7 + cc + 3; if (w >= HDIM) w -= HDIM;
        __half hi, lo; f16_split(x[c * HWSZ + h * HDIM + w], hi, lo);
        int off = (wl_ * 64 + t) * XST + c;
        Xh[off] = hi; Xl[off] = lo;
    }
    for (int idx = tid; idx < 30 * CCH; idx += 512) {    // pad rows 49..63, 113..127
        int pr = idx / CCH, c = idx - pr * CCH;
        int row = (pr < 15) ? (49 + pr) : (98 + pr);
        int off = row * XST + c;
        Xh[off] = __float2half(0.f); Xl[off] = __float2half(0.f);
    }

    const uint32_t aoffh = sb + (uint32_t)(mw * 32 + (lane & 15)) * (XST * 2) + (lane >> 4) * 16;
    const uint32_t aoffl = aoffh + 51200;
    const uint32_t bfrag = (uint32_t)(nw * 24 + (lane & 7)) * (XST * 2) + ((lane >> 3) & 1) * 16;

    for (int s = 0; s < 6; s++) {
        if (s + 1 < 6) { stageW(s + 1, (s + 1) & 1); CPA_WAIT(1); }
        else           { CPA_WAIT(0); }
        __syncthreads();

        const uint32_t boff = sb + 102400 + (uint32_t)(s & 1) * 38400 + bfrag;

        float acc[2][3][4];
        #pragma unroll
        for (int a = 0; a < 2; a++)
            #pragma unroll
            for (int b = 0; b < 3; b++)
                #pragma unroll
                for (int e = 0; e < 4; e++) acc[a][b][e] = 0.f;

        #pragma unroll 2
        for (int k = 0; k < 12; k++) {
            uint32_t ah[2][4], al[2][4], bh[3][2];
            #pragma unroll
            for (int mt = 0; mt < 2; mt++) {
                LDSM4(ah[mt], aoffh + mt * 16 * (XST * 2) + k * 32);
                LDSM4(al[mt], aoffl + mt * 16 * (XST * 2) + k * 32);
            }
            #pragma unroll
            for (int nt = 0; nt < 3; nt++)
                LDSM2(bh[nt], boff + nt * 8 * (XST * 2) + k * 32);
            #pragma unroll
            for (int mt = 0; mt < 2; mt++)
                #pragma unroll
                for (int nt = 0; nt < 3; nt++)
                    MMA_F16(acc[mt][nt], ah[mt], bh[nt]);
            #pragma unroll
            for (int mt = 0; mt < 2; mt++)
                #pragma unroll
                for (int nt = 0; nt < 3; nt++)
                    MMA_F16(acc[mt][nt], al[mt], bh[nt]);
        }

        // epilogue: fp32 scratch with bias (+ q scale)
        const int g = lane >> 2, c2 = (lane & 3) * 2;
        #pragma unroll
        for (int mt = 0; mt < 2; mt++)
            #pragma unroll
            for (int nt = 0; nt < 3; nt++) {
                int col = s * 96 + nw * 24 + nt * 8 + c2;
                int buf = col / 192, ch = col - buf * 192;
                float scl = (buf == 0) ? 0.17677669529663687f : 1.0f;
                float* base = (buf == 0) ? g_q : (buf == 1) ? g_k : g_v;
                float b0 = qkvB[col], b1 = qkvB[col + 1];
                #pragma unroll
                for (int rr = 0; rr < 2; rr++) {
                    int row = mw * 32 + mt * 16 + g + rr * 8;
                    int wl_ = row >> 6, t = row & 63;
                    if (t < NT) {
                        float2 o;
                        o.x = (acc[mt][nt][rr * 2 + 0] + b0) * scl;
                        o.y = (acc[mt][nt][rr * 2 + 1] + b1) * scl;
                        *(float2*)(base + ((size_t)(pair * 2 + wl_) * NT + t) * CCH + ch) = o;
                    }
                }
            }
        __syncthreads();
    }
}

// ============================================================================
// Kernel 2: attention — all 6 heads per phase, cp.async q/k/v load
// smem floats: qs|ks|vs (28812) | sc 6*2720 (16320) | mreg
// ============================================================================
constexpr int ATTN_FLOATS = 3 * NT * CPAD + 6 * SCH + 64;

__global__ __launch_bounds__(512, 1)
void attn_kernel(const float* __restrict__ table)
{
    extern __shared__ float smf[];
    float* qs = smf;
    float* ks = qs + NT * CPAD;
    float* vs = ks + NT * CPAD;
    float* sc = vs + NT * CPAD;
    int*   mreg = (int*)(sc + 6 * SCH);
    const uint32_t sb = smem_u32(smf);

    const int tid  = threadIdx.x;
    const int lane = tid & 31;
    const int warp = tid >> 5;
    const int win = blockIdx.x;
    const int wy = win >> 6, wx = win & 63;

    // cp.async q/k/v into smem (16B granules, CPAD row stride)
    {
        const float4* gq = (const float4*)(g_q + (size_t)win * NT * CCH);
        const float4* gk = (const float4*)(g_k + (size_t)win * NT * CCH);
        const float4* gv = (const float4*)(g_v + (size_t)win * NT * CCH);
        for (int i4 = tid; i4 < NT * 48; i4 += 512) {
            int t = i4 / 48, c4 = i4 - t * 48;
            uint32_t d = sb + (uint32_t)t * (CPAD * 4) + c4 * 16;
            CPA16(d, gq + i4);
            CPA16(d + NT * CPAD * 4, gk + i4);
            CPA16(d + 2 * NT * CPAD * 4, gv + i4);
        }
        CPA_COMMIT();
    }
    if (tid < NT) {
        int r = tid / 7, cc = tid - (tid / 7) * 7;
        int hs = wy * 7 + r, ws = wx * 7 + cc;
        int rb = (hs >= 441) + (hs >= 445);
        int cb = (ws >= 441) + (ws >= 445);
        mreg[tid] = rb * 3 + cb;
    }
    CPA_WAIT(0);
    __syncthreads();

    __half* aoim = g_ao + (size_t)(win >> 1) * 2 * 128 * XST;
    const int rowbase = (win & 1) * 64;

    // ---- Phase A: scores for all heads (78 warp-tasks) ----
    for (int task = warp; task < 78; task += 16) {
        const int h = task / 13, ig = task - h * 13;
        const int kb = h * HD;
        float* shc = sc + h * SCH;
        int i0 = ig * 4;
        float a2[4][2] = {{0,0},{0,0},{0,0},{0,0}};
        const int j2 = lane + 32;
        const bool j2v = (j2 < NT);
        #pragma unroll
        for (int d = 0; d < HD; d += 4) {
            float4 k0 = *(const float4*)(ks + lane * CPAD + kb + d);
            float4 k1 = make_float4(0.f, 0.f, 0.f, 0.f);
            if (j2v) k1 = *(const float4*)(ks + j2 * CPAD + kb + d);
            #pragma unroll
            for (int ii = 0; ii < 4; ii++) {
                const float4 q4 = *(const float4*)(qs + (i0 + ii) * CPAD + kb + d);
                a2[ii][0] += q4.x*k0.x + q4.y*k0.y + q4.z*k0.z + q4.w*k0.w;
                a2[ii][1] += q4.x*k1.x + q4.y*k1.y + q4.z*k1.z + q4.w*k1.w;
            }
        }
        #pragma unroll
        for (int ii = 0; ii < 4; ii++) {
            int i = i0 + ii;
            if (i >= NT) break;
            int ri = i / 7, ci = i - ri * 7;
            int mi = mreg[i];
            #pragma unroll
            for (int jj = 0; jj < 2; jj++) {
                int j = lane + jj * 32;
                if (j >= NT) continue;
                int rj = j / 7, cj = j - rj * 7;
                int rel = (ri - rj) + (ci - cj);
                if (rel < 0) rel += 169;
                float bi = table[rel * NHEAD + h];
                float msk = (mi == mreg[j]) ? 0.0f : -100.0f;
                shc[i * SROW + j] = a2[ii][jj] + bi + msk;
            }
        }
    }
    __syncthreads();

    // ---- Phase B: softmax for all heads (294 row-tasks) ----
    for (int task = warp; task < 294; task += 16) {
        const int h = task / 49, i = task - h * 49;
        float* shc = sc + h * SCH;
        float v0 = shc[i * SROW + lane];
        float v1 = (lane + 32 < NT) ? shc[i * SROW + lane + 32] : -1e30f;
        float mx = fmaxf(v0, v1);
        #pragma unroll
        for (int off = 16; off; off >>= 1)
            mx = fmaxf(mx, __shfl_xor_sync(0xffffffffu, mx, off));
        float e0 = __expf(v0 - mx);
        float e1 = (lane + 32 < NT) ? __expf(v1 - mx) : 0.0f;
        float sum = e0 + e1;
        #pragma unroll
        for (int off = 16; off; off >>= 1)
            sum += __shfl_xor_sync(0xffffffffu, sum, off);
        float inv = 1.0f / sum;
        shc[i * SROW + lane] = e0 * inv;
        if (lane + 32 < NT) shc[i * SROW + lane + 32] = e1 * inv;
    }
    __syncthreads();

    // ---- Phase C: P @ V for all heads (78 warp-tasks) ----
    for (int task = warp; task < 78; task += 16) {
        const int h = task / 13, ig = task - h * 13;
        const int kb = h * HD;
        float* shc = sc + h * SCH;
        const int vb = kb + lane;
        int i0 = ig * 4;
        float acc2[4] = {0.f, 0.f, 0.f, 0.f};
        #pragma unroll 4
        for (int j = 0; j < 48; j += 4) {
            float4 p0 = *(const float4*)(shc + (i0 + 0) * SROW + j);
            float4 p1 = *(const float4*)(shc + (i0 + 1) * SROW + j);
            float4 p2 = *(const float4*)(shc + (i0 + 2) * SROW + j);
            float4 p3 = *(const float4*)(shc + (i0 + 3) * SROW + j);
            #pragma unroll
            for (int jj = 0; jj < 4; jj++) {
                float vv = vs[(j + jj) * CPAD + vb];
                acc2[0] += ((const float*)&p0)[jj] * vv;
                acc2[1] += ((const float*)&p1)[jj] * vv;
                acc2[2] += ((const float*)&p2)[jj] * vv;
                acc2[3] += ((const float*)&p3)[jj] * vv;
            }
        }
        {
            float vv = vs[48 * CPAD + vb];
            acc2[0] += shc[(i0 + 0) * SROW + 48] * vv;
            acc2[1] += shc[(i0 + 1) * SROW + 48] * vv;
            acc2[2] += shc[(i0 + 2) * SROW + 48] * vv;
            acc2[3] += shc[(i0 + 3) * SROW + 48] * vv;
        }
        #pragma unroll
        for (int ii = 0; ii < 4; ii++) {
            if (i0 + ii < NT) {
                __half hi, lo; f16_split(acc2[ii], hi, lo);
                int off = (rowbase + i0 + ii) * XST + kb + lane;
                aoim[off] = hi;
                aoim[128 * XST + off] = lo;
            }
        }
    }
}

// ============================================================================
// Kernel 3: proj GEMM — single stage of all 192 oc, cp.async prefetch
// smem: Ah 51200 | Al 51200 | W 76800 = 179200 ; ds overlays Ah/Al
// ============================================================================
#define PROJ_SMEM 179200

__global__ __launch_bounds__(512, 1)
void proj_kernel(const float* __restrict__ projB, float* __restrict__ out)
{
    extern __shared__ char smem[];
    __half* Ws = (__half*)(smem + 102400);
    float* ds = (float*)smem;
    const uint32_t sb = smem_u32(smem);
    const int tid = threadIdx.x, lane = tid & 31, warp = tid >> 5;
    const int pair = blockIdx.x;
    const int mw = warp & 3, nw = warp >> 2;

    // cp.async: A images (linear) + all proj weights
    {
        const uint4* s = (const uint4*)(g_ao + (size_t)pair * 2 * 128 * XST);
        for (int i = tid; i < 6400; i += 512)
            CPA16(sb + i * 16, s + i);
        for (int i = tid; i < 4608; i += 512) {
            int r = i / 24, p = i - r * 24;
            CPA16(sb + 102400 + (uint32_t)r * (XST * 2) + p * 16,
                  (const char*)(g_projw + r * 192) + p * 16);
        }
        CPA_COMMIT();
    }
    CPA_WAIT(0);
    __syncthreads();

    const uint32_t aoffh = sb +          (uint32_t)(mw * 32 + (lane & 15)) * (XST * 2) + (lane >> 4) * 16;
    const uint32_t aoffl = aoffh + 51200;
    const uint32_t boff  = sb + 102400 + (uint32_t)(nw * 48 + (lane & 7)) * (XST * 2) + ((lane >> 3) & 1) * 16;

    float acc[2][6][4];
    #pragma unroll
    for (int a = 0; a < 2; a++)
        #pragma unroll
        for (int b = 0; b < 6; b++)
            #pragma unroll
            for (int e = 0; e < 4; e++) acc[a][b][e] = 0.f;

    #pragma unroll 2
    for (int k = 0; k < 12; k++) {
        uint32_t ah[2][4], al[2][4], bh[6][2];
        #pragma unroll
        for (int mt = 0; mt < 2; mt++) {
            LDSM4(ah[mt], aoffh + mt * 16 * (XST * 2) + k * 32);
            LDSM4(al[mt], aoffl + mt * 16 * (XST * 2) + k * 32);
        }
        #pragma unroll
        for (int nt = 0; nt < 6; nt++)
            LDSM2(bh[nt], boff + nt * 8 * (XST * 2) + k * 32);
        #pragma unroll
        for (int mt = 0; mt < 2; mt++)
            #pragma unroll
            for (int nt = 0; nt < 6; nt++)
                MMA_F16(acc[mt][nt], ah[mt], bh[nt]);
        #pragma unroll
        for (int mt = 0; mt < 2; mt++)
            #pragma unroll
            for (int nt = 0; nt < 6; nt++)
                MMA_F16(acc[mt][nt], al[mt], bh[nt]);
    }
    __syncthreads();

    // write accums into ds[c][tok2] (+bias); ds overlays A region (A dead now)
    {
        const int g = lane >> 2, c2 = (lane & 3) * 2;
        #pragma unroll
        for (int mt = 0; mt < 2; mt++)
            #pragma unroll
            for (int nt = 0; nt < 6; nt++) {
                int col = nw * 48 + nt * 8 + c2;
                float b0 = projB[col], b1 = projB[col + 1];
                #pragma unroll
                for (int rr = 0; rr < 2; rr++) {
                    int row = mw * 32 + mt * 16 + g + rr * 8;
                    int wl_ = row >> 6, t = row & 63;
                    if (t < NT) {
                        int tt = wl_ * 49 + t;
                        ds[col * 100 + tt]       = acc[mt][nt][rr * 2 + 0] + b0;
                        ds[(col + 1) * 100 + tt] = acc[mt][nt][rr * 2 + 1] + b1;
                    }
                }
            }
    }
    __syncthreads();

    // scatter with reverse shift (coalesced along w)
    for (int idx = tid; idx < CCH * 98; idx += 512) {
        int c = idx / 98, tt = idx - c * 98;
        int wl_ = tt / 49, t = tt - wl_ * 49;
        int win = pair * 2 + wl_, wy = win >> 6, wx = win & 63;
        int r = t / 7, cc = t - r * 7;
        int h = wy * 7 + r + 3; if (h >= HDIM) h -= HDIM;
        int w = wx * 7 + cc + 3; if (w >= HDIM) w -= HDIM;
        out[c * HWSZ + h * HDIM + w] = ds[c * 100 + tt];
    }
}

// ============================================================================
extern "C" void kernel_launch(void* const* d_in, const int* in_sizes, int n_in,
                              void* d_out, int out_size) {
    const float* x     = (const float*)d_in[0];
    const float* qkvW  = (const float*)d_in[1];
    const float* qkvB  = (const float*)d_in[2];
    const float* projW = (const float*)d_in[3];
    const float* projB = (const float*)d_in[4];
    const float* table = (const float*)d_in[5];
    float* out = (float*)d_out;

    cudaFuncSetAttribute(qkv_kernel,  cudaFuncAttributeMaxDynamicSharedMemorySize, QKV_SMEM);
    cudaFuncSetAttribute(proj_kernel, cudaFuncAttributeMaxDynamicSharedMemorySize, PROJ_SMEM);
    cudaFuncSetAttribute(attn_kernel, cudaFuncAttributeMaxDynamicSharedMemorySize, ATTN_FLOATS * 4);

    prep_kernel<<<576, 256>>>(qkvW, projW);
    qkv_kernel<<<NPAIR, 512, QKV_SMEM>>>(x, qkvB);
    attn_kernel<<<NWIN, 512, ATTN_FLOATS * 4>>>(table);
    proj_kernel<<<NPAIR, 512, PROJ_SMEM>>>(projB, out);
}

// round 17
// speedup vs baseline: 1.4180x; 1.0045x over previous
#include <cuda_runtime.h>
#include <cuda_fp16.h>
#include <cstdint>

#define NWIN  4096
#define NPAIR 2048
#define CCH   192
#define HDIM  448
#define HWSZ  (448*448)
#define NHEAD 6
#define HD    32
#define NT    49
#define CPAD  196
#define SROW  52
#define SCH   2720     // per-head score buffer (floats)
#define XST   200      // fp16 row stride for mma tiles (400B)

// ---- device scratch ----
__device__ __align__(16) float g_q[(size_t)NWIN * NT * CCH];
__device__ __align__(16) float g_k[(size_t)NWIN * NT * CCH];
__device__ __align__(16) float g_v[(size_t)NWIN * NT * CCH];
__device__ __align__(16) __half g_qkvw[576 * 192];
__device__ __align__(16) __half g_projw[192 * 192];

// ---- helpers ----
__device__ __forceinline__ uint32_t smem_u32(const void* p) {
    uint32_t a;
    asm("{ .reg .u64 t; cvta.to.shared.u64 t, %1; cvt.u32.u64 %0, t; }" : "=r"(a) : "l"(p));
    return a;
}
#define LDSM4(r, a) asm volatile("ldmatrix.sync.aligned.m8n8.x4.shared.b16 {%0,%1,%2,%3}, [%4];" \
    : "=r"((r)[0]), "=r"((r)[1]), "=r"((r)[2]), "=r"((r)[3]) : "r"(a))
#define LDSM2(r, a) asm volatile("ldmatrix.sync.aligned.m8n8.x2.shared.b16 {%0,%1}, [%2];" \
    : "=r"((r)[0]), "=r"((r)[1]) : "r"(a))
#define MMA_F16(d, A, B) asm volatile( \
    "mma.sync.aligned.m16n8k16.row.col.f32.f16.f16.f32 " \
    "{%0,%1,%2,%3}, {%4,%5,%6,%7}, {%8,%9}, {%0,%1,%2,%3};" \
    : "+f"((d)[0]), "+f"((d)[1]), "+f"((d)[2]), "+f"((d)[3]) \
    : "r"((A)[0]), "r"((A)[1]), "r"((A)[2]), "r"((A)[3]), "r"((B)[0]), "r"((B)[1]))

#define CPA16(dst, src) asm volatile("cp.async.cg.shared.global [%0], [%1], 16;" \
    :: "r"(dst), "l"(__cvta_generic_to_global(src)) : "memory")
#define CPA_COMMIT() asm volatile("cp.async.commit_group;" ::: "memory")
#define CPA_WAIT(N)  asm volatile("cp.async.wait_group %0;" :: "n"(N) : "memory")

__device__ __forceinline__ void f16_split(float v, __half& hi, __half& lo) {
    hi = __float2half(v);
    lo = __float2half(v - __half2float(hi));
}

// ============================================================================
// Kernel 0: weight prep (fp32 -> fp16, dense row-major)
// ============================================================================
__global__ void prep_kernel(const float* __restrict__ qkvW, const float* __restrict__ projW) {
    int i = blockIdx.x * blockDim.x + threadIdx.x;
    if (i < 576 * 192) {
        g_qkvw[i] = __float2half(qkvW[i]);
    } else {
        i -= 576 * 192;
        if (i < 192 * 192) g_projw[i] = __float2half(projW[i]);
    }
}

// ============================================================================
// Kernel 1: QKV GEMM — unchanged from 1265µs baseline
// smem: Xh 51200 | Xl 51200 | W0 38400 | W1 38400 = 179200
// ============================================================================
#define QKV_SMEM 179200

__global__ __launch_bounds__(512, 1)
void qkv_kernel(const float* __restrict__ x, const float* __restrict__ qkvB)
{
    extern __shared__ char smem[];
    __half* Xh = (__half*)smem;
    __half* Xl = (__half*)(smem + 51200);
    const uint32_t sb = smem_u32(smem);
    const int tid = threadIdx.x, lane = tid & 31, warp = tid >> 5;
    const int pair = blockIdx.x;
    const int mw = warp & 3, nw = warp >> 2;

    auto stageW = [&](int s, int buf) {
        const uint32_t dstb = sb + 102400 + (uint32_t)buf * 38400;
        const __half* src = g_qkvw + s * 96 * 192;
        for (int i = tid; i < 2304; i += 512) {
            int r = i / 24, p = i - r * 24;
            CPA16(dstb + (uint32_t)r * (XST * 2) + p * 16, (const char*)(src + r * 192) + p * 16);
        }
        CPA_COMMIT();
    };

    stageW(0, 0);

    for (int idx = tid; idx < 2 * NT * CCH; idx += 512) {
        int wl_ = idx / (NT * CCH), rem = idx - wl_ * NT * CCH;
        int c = rem / NT, t = rem - c * NT;
        int win = pair * 2 + wl_, wy = win >> 6, wx = win & 63;
        int r = t / 7, cc = t - r * 7;
        int h = wy * 7 + r + 3; if (h >= HDIM) h -= HDIM;
        int w = wx * 7 + cc + 3; if (w >= HDIM) w -= HDIM;
        __half hi, lo; f16_split(x[c * HWSZ + h * HDIM + w], hi, lo);
        int off = (wl_ * 64 + t) * XST + c;
        Xh[off] = hi; Xl[off] = lo;
    }
    for (int idx = tid; idx < 30 * CCH; idx += 512) {
        int pr = idx / CCH, c = idx - pr * CCH;
        int row = (pr < 15) ? (49 + pr) : (98 + pr);
        int off = row * XST + c;
        Xh[off] = __float2half(0.f); Xl[off] = __float2half(0.f);
    }

    const uint32_t aoffh = sb + (uint32_t)(mw * 32 + (lane & 15)) * (XST * 2) + (lane >> 4) * 16;
    const uint32_t aoffl = aoffh + 51200;
    const uint32_t bfrag = (uint32_t)(nw * 24 + (lane & 7)) * (XST * 2) + ((lane >> 3) & 1) * 16;

    for (int s = 0; s < 6; s++) {
        if (s + 1 < 6) { stageW(s + 1, (s + 1) & 1); CPA_WAIT(1); }
        else           { CPA_WAIT(0); }
        __syncthreads();

        const uint32_t boff = sb + 102400 + (uint32_t)(s & 1) * 38400 + bfrag;

        float acc[2][3][4];
        #pragma unroll
        for (int a = 0; a < 2; a++)
            #pragma unroll
            for (int b = 0; b < 3; b++)
                #pragma unroll
                for (int e = 0; e < 4; e++) acc[a][b][e] = 0.f;

        #pragma unroll 2
        for (int k = 0; k < 12; k++) {
            uint32_t ah[2][4], al[2][4], bh[3][2];
            #pragma unroll
            for (int mt = 0; mt < 2; mt++) {
                LDSM4(ah[mt], aoffh + mt * 16 * (XST * 2) + k * 32);
                LDSM4(al[mt], aoffl + mt * 16 * (XST * 2) + k * 32);
            }
            #pragma unroll
            for (int nt = 0; nt < 3; nt++)
                LDSM2(bh[nt], boff + nt * 8 * (XST * 2) + k * 32);
            #pragma unroll
            for (int mt = 0; mt < 2; mt++)
                #pragma unroll
                for (int nt = 0; nt < 3; nt++)
                    MMA_F16(acc[mt][nt], ah[mt], bh[nt]);
            #pragma unroll
            for (int mt = 0; mt < 2; mt++)
                #pragma unroll
                for (int nt = 0; nt < 3; nt++)
                    MMA_F16(acc[mt][nt], al[mt], bh[nt]);
        }

        const int g = lane >> 2, c2 = (lane & 3) * 2;
        #pragma unroll
        for (int mt = 0; mt < 2; mt++)
            #pragma unroll
            for (int nt = 0; nt < 3; nt++) {
                int col = s * 96 + nw * 24 + nt * 8 + c2;
                int buf = col / 192, ch = col - buf * 192;
                float scl = (buf == 0) ? 0.17677669529663687f : 1.0f;
                float* base = (buf == 0) ? g_q : (buf == 1) ? g_k : g_v;
                float b0 = qkvB[col], b1 = qkvB[col + 1];
                #pragma unroll
                for (int rr = 0; rr < 2; rr++) {
                    int row = mw * 32 + mt * 16 + g + rr * 8;
                    int wl_ = row >> 6, t = row & 63;
                    if (t < NT) {
                        float2 o;
                        o.x = (acc[mt][nt][rr * 2 + 0] + b0) * scl;
                        o.y = (acc[mt][nt][rr * 2 + 1] + b1) * scl;
                        *(float2*)(base + ((size_t)(pair * 2 + wl_) * NT + t) * CCH + ch) = o;
                    }
                }
            }
        __syncthreads();
    }
}

// ============================================================================
// Kernel 2: attention + proj + scatter (per window, 512 thr)
// smem (bytes):
//   0       qs|ks|vs fp32 (3*38416=115248)
//           - ao fp16 images overlay qs+ks after Phase A (hi@0, lo@25600)
//           - ds (38400) overlays vs after Phase C
//   115248  sc (6*2720*4 = 65280); W1 overlays after Phase C
//   180528  W0 (38400)
//   218928  mreg (256)
// ============================================================================
#define SC_OFF   115248
#define W0_OFF   180528
#define MREG_OFF 218928
#define AP_SMEM  219184

__global__ __launch_bounds__(512, 1)
void attnproj_kernel(const float* __restrict__ table,
                     const float* __restrict__ projB,
                     float* __restrict__ out)
{
    extern __shared__ char smem[];
    const uint32_t sb = smem_u32(smem);
    float* qs = (float*)smem;
    float* ks = qs + NT * CPAD;
    float* vs = ks + NT * CPAD;
    float* sc = (float*)(smem + SC_OFF);
    __half* aoim = (__half*)smem;                 // overlays qs/ks after Phase A
    float* ds = vs;                               // overlays vs after Phase C
    int*   mreg = (int*)(smem + MREG_OFF);

    const int tid  = threadIdx.x;
    const int lane = tid & 31;
    const int warp = tid >> 5;
    const int mw = warp & 3, nw = warp >> 2;
    const int win = blockIdx.x;
    const int wy = win >> 6, wx = win & 63;

    // prefetch proj W0 (oc 0..95) + q/k/v (one commit group)
    for (int i = tid; i < 2304; i += 512) {
        int r = i / 24, p = i - r * 24;
        CPA16(sb + W0_OFF + (uint32_t)r * (XST * 2) + p * 16,
              (const char*)(g_projw + r * 192) + p * 16);
    }
    {
        const float4* gq = (const float4*)(g_q + (size_t)win * NT * CCH);
        const float4* gk = (const float4*)(g_k + (size_t)win * NT * CCH);
        const float4* gv = (const float4*)(g_v + (size_t)win * NT * CCH);
        for (int i4 = tid; i4 < NT * 48; i4 += 512) {
            int t = i4 / 48, c4 = i4 - t * 48;
            uint32_t d = sb + (uint32_t)t * (CPAD * 4) + c4 * 16;
            CPA16(d, gq + i4);
            CPA16(d + NT * CPAD * 4, gk + i4);
            CPA16(d + 2 * NT * CPAD * 4, gv + i4);
        }
        CPA_COMMIT();
    }
    if (tid < NT) {
        int r = tid / 7, cc = tid - (tid / 7) * 7;
        int hs = wy * 7 + r, ws = wx * 7 + cc;
        int rb = (hs >= 441) + (hs >= 445);
        int cb = (ws >= 441) + (ws >= 445);
        mreg[tid] = rb * 3 + cb;
    }
    CPA_WAIT(0);
    __syncthreads();

    // ---- Phase A: scores for all heads (78 warp-tasks) ----
    for (int task = warp; task < 78; task += 16) {
        const int h = task / 13, ig = task - h * 13;
        const int kb = h * HD;
        float* shc = sc + h * SCH;
        int i0 = ig * 4;
        float a2[4][2] = {{0,0},{0,0},{0,0},{0,0}};
        const int j2 = lane + 32;
        const bool j2v = (j2 < NT);
        #pragma unroll
        for (int d = 0; d < HD; d += 4) {
            float4 k0 = *(const float4*)(ks + lane * CPAD + kb + d);
            float4 k1 = make_float4(0.f, 0.f, 0.f, 0.f);
            if (j2v) k1 = *(const float4*)(ks + j2 * CPAD + kb + d);
            #pragma unroll
            for (int ii = 0; ii < 4; ii++) {
                const float4 q4 = *(const float4*)(qs + (i0 + ii) * CPAD + kb + d);
                a2[ii][0] += q4.x*k0.x + q4.y*k0.y + q4.z*k0.z + q4.w*k0.w;
                a2[ii][1] += q4.x*k1.x + q4.y*k1.y + q4.z*k1.z + q4.w*k1.w;
            }
        }
        #pragma unroll
        for (int ii = 0; ii < 4; ii++) {
            int i = i0 + ii;
            if (i >= NT) break;
            int ri = i / 7, ci = i - ri * 7;
            int mi = mreg[i];
            #pragma unroll
            for (int jj = 0; jj < 2; jj++) {
                int j = lane + jj * 32;
                if (j >= NT) continue;
                int rj = j / 7, cj = j - rj * 7;
                int rel = (ri - rj) + (ci - cj);
                if (rel < 0) rel += 169;
                float bi = table[rel * NHEAD + h];
                float msk = (mi == mreg[j]) ? 0.0f : -100.0f;
                shc[i * SROW + j] = a2[ii][jj] + bi + msk;
            }
        }
    }
    __syncthreads();

    // ---- Phase B: softmax for all heads (294 row-tasks) ----
    for (int task = warp; task < 294; task += 16) {
        const int h = task / 49, i = task - h * 49;
        float* shc = sc + h * SCH;
        float v0 = shc[i * SROW + lane];
        float v1 = (lane + 32 < NT) ? shc[i * SROW + lane + 32] : -1e30f;
        float mx = fmaxf(v0, v1);
        #pragma unroll
        for (int off = 16; off; off >>= 1)
            mx = fmaxf(mx, __shfl_xor_sync(0xffffffffu, mx, off));
        float e0 = __expf(v0 - mx);
        float e1 = (lane + 32 < NT) ? __expf(v1 - mx) : 0.0f;
        float sum = e0 + e1;
        #pragma unroll
        for (int off = 16; off; off >>= 1)
            sum += __shfl_xor_sync(0xffffffffu, sum, off);
        float inv = 1.0f / sum;
        shc[i * SROW + lane] = e0 * inv;
        if (lane + 32 < NT) shc[i * SROW + lane + 32] = e1 * inv;
    }
    __syncthreads();

    // ---- Phase C: P @ V, write ao fp16 images into dead qs/ks region ----
    for (int task = warp; task < 78; task += 16) {
        const int h = task / 13, ig = task - h * 13;
        const int kb = h * HD;
        float* shc = sc + h * SCH;
        const int vb = kb + lane;
        int i0 = ig * 4;
        float acc2[4] = {0.f, 0.f, 0.f, 0.f};
        #pragma unroll 4
        for (int j = 0; j < 48; j += 4) {
            float4 p0 = *(const float4*)(shc + (i0 + 0) * SROW + j);
            float4 p1 = *(const float4*)(shc + (i0 + 1) * SROW + j);
            float4 p2 = *(const float4*)(shc + (i0 + 2) * SROW + j);
            float4 p3 = *(const float4*)(shc + (i0 + 3) * SROW + j);
            #pragma unroll
            for (int jj = 0; jj < 4; jj++) {
                float vv = vs[(j + jj) * CPAD + vb];
                acc2[0] += ((const float*)&p0)[jj] * vv;
                acc2[1] += ((const float*)&p1)[jj] * vv;
                acc2[2] += ((const float*)&p2)[jj] * vv;
                acc2[3] += ((const float*)&p3)[jj] * vv;
            }
        }
        {
            float vv = vs[48 * CPAD + vb];
            acc2[0] += shc[(i0 + 0) * SROW + 48] * vv;
            acc2[1] += shc[(i0 + 1) * SROW + 48] * vv;
            acc2[2] += shc[(i0 + 2) * SROW + 48] * vv;
            acc2[3] += shc[(i0 + 3) * SROW + 48] * vv;
        }
        #pragma unroll
        for (int ii = 0; ii < 4; ii++) {
            if (i0 + ii < NT) {
                __half hi, lo; f16_split(acc2[ii], hi, lo);
                int off = (i0 + ii) * XST + kb + lane;
                aoim[off] = hi;
                aoim[12800 + off] = lo;
            }
        }
    }
    __syncthreads();

    // ---- prefetch W1 (oc 96..191) into dead sc region ----
    for (int i = tid; i < 2304; i += 512) {
        int r = i / 24, p = i - r * 24;
        CPA16(sb + SC_OFF + (uint32_t)r * (XST * 2) + p * 16,
              (const char*)(g_projw + (96 + r) * 192) + p * 16);
    }
    CPA_COMMIT();

    // ---- proj GEMM: M=64, 2 oc-stages of 96, fp16 2-product ----
    const uint32_t aoffh = sb + (uint32_t)(mw * 16 + (lane & 15)) * (XST * 2) + (lane >> 4) * 16;
    const uint32_t aoffl = aoffh + 25600;
    const uint32_t bfrag = (uint32_t)(nw * 24 + (lane & 7)) * (XST * 2) + ((lane >> 3) & 1) * 16;

    float pacc[2][3][4];
    #pragma unroll
    for (int s = 0; s < 2; s++)
        #pragma unroll
        for (int b = 0; b < 3; b++)
            #pragma unroll
            for (int e = 0; e < 4; e++) pacc[s][b][e] = 0.f;

    // stage 0 (W0 already resident)
    {
        const uint32_t boff = sb + W0_OFF + bfrag;
        #pragma unroll 2
        for (int k = 0; k < 12; k++) {
            uint32_t ah[4], al[4], bh[3][2];
            LDSM4(ah, aoffh + k * 32);
            LDSM4(al, aoffl + k * 32);
            #pragma unroll
            for (int nt = 0; nt < 3; nt++)
                LDSM2(bh[nt], boff + nt * 8 * (XST * 2) + k * 32);
            #pragma unroll
            for (int nt = 0; nt < 3; nt++) MMA_F16(pacc[0][nt], ah, bh[nt]);
            #pragma unroll
            for (int nt = 0; nt < 3; nt++) MMA_F16(pacc[0][nt], al, bh[nt]);
        }
    }
    CPA_WAIT(0);
    __syncthreads();
    // stage 1 (W1 in sc region)
    {
        const uint32_t boff = sb + SC_OFF + bfrag;
        #pragma unroll 2
        for (int k = 0; k < 12; k++) {
            uint32_t ah[4], al[4], bh[3][2];
            LDSM4(ah, aoffh + k * 32);
            LDSM4(al, aoffl + k * 32);
            #pragma unroll
            for (int nt = 0; nt < 3; nt++)
                LDSM2(bh[nt], boff + nt * 8 * (XST * 2) + k * 32);
            #pragma unroll
            for (int nt = 0; nt < 3; nt++) MMA_F16(pacc[1][nt], ah, bh[nt]);
            #pragma unroll
            for (int nt = 0; nt < 3; nt++) MMA_F16(pacc[1][nt], al, bh[nt]);
        }
    }

    // write ds[c][tok] (+bias); ds overlays vs (dead after Phase C)
    {
        const int g = lane >> 2, c2 = (lane & 3) * 2;
        #pragma unroll
        for (int s = 0; s < 2; s++)
            #pragma unroll
            for (int nt = 0; nt < 3; nt++) {
                int col = s * 96 + nw * 24 + nt * 8 + c2;
                float b0 = projB[col], b1 = projB[col + 1];
                #pragma unroll
                for (int rr = 0; rr < 2; rr++) {
                    int row = mw * 16 + g + rr * 8;
                    if (row < NT) {
                        ds[col * 50 + row]       = pacc[s][nt][rr * 2 + 0] + b0;
                        ds[(col + 1) * 50 + row] = pacc[s][nt][rr * 2 + 1] + b1;
                    }
                }
            }
    }
    __syncthreads();

    // scatter with reverse shift
    for (int idx = tid; idx < CCH * NT; idx += 512) {
        int c = idx / NT, t = idx - c * NT;
        int r = t / 7, cc = t - r * 7;
        int h = wy * 7 + r + 3; if (h >= HDIM) h -= HDIM;
        int w = wx * 7 + cc + 3; if (w >= HDIM) w -= HDIM;
        out[c * HWSZ + h * HDIM + w] = ds[c * 50 + t];
    }
}

// ============================================================================
extern "C" void kernel_launch(void* const* d_in, const int* in_sizes, int n_in,
                              void* d_out, int out_size) {
    const float* x     = (const float*)d_in[0];
    const float* qkvW  = (const float*)d_in[1];
    const float* qkvB  = (const float*)d_in[2];
    const float* projW = (const float*)d_in[3];
    const float* projB = (const float*)d_in[4];
    const float* table = (const float*)d_in[5];
    float* out = (float*)d_out;

    cudaFuncSetAttribute(qkv_kernel,      cudaFuncAttributeMaxDynamicSharedMemorySize, QKV_SMEM);
    cudaFuncSetAttribute(attnproj_kernel, cudaFuncAttributeMaxDynamicSharedMemorySize, AP_SMEM);

    prep_kernel<<<576, 256>>>(qkvW, projW);
    qkv_kernel<<<NPAIR, 512, QKV_SMEM>>>(x, qkvB);
    attnproj_kernel<<<NWIN, 512, AP_SMEM>>>(table, projB, out);
}